// round 2
// baseline (speedup 1.0000x reference)
#include <cuda_runtime.h>
#include <cuda_bf16.h>
#include <math.h>

#define T_LEN 4096
#define TR_LEN 1024
#define DIM 1536
#define NH 12
#define DH 128

// ---------------- scratch (device globals; no allocation allowed) ----------------
__device__ float g_qlin[T_LEN * DIM];   // q_lin -> rmsnorm(q) in place
__device__ float g_klin[T_LEN * DIM];   // k_lin -> rmsnorm(k) -> rope(k) in place
__device__ float g_vlin[T_LEN * DIM];   // v
__device__ float g_krlin[TR_LEN * DIM]; // ref k_lin -> rmsnorm in place
__device__ float g_vrlin[TR_LEN * DIM]; // ref v
__device__ float g_qrope[T_LEN * DIM];  // rope(q) out of place (unroped q needed for ref attn)
__device__ float g_attn[T_LEN * DIM];   // main_out + ref_out accumulator

// ---------------- GEMM: C[M x 1536] = A[M x 1536] @ W[1536 x 1536] + bias ----------------
// Tile 128x128x16, 256 threads, 8x8 microkernel, A stored k-major (transposed) in smem.
__global__ __launch_bounds__(256) void gemm_bias_kernel(
    const float* __restrict__ A, const float* __restrict__ W,
    const float* __restrict__ bias, float* __restrict__ C)
{
    __shared__ float As[16 * 132];  // As[k][m], pitch 132 (pad for banks, float4-aligned)
    __shared__ float Bs[16 * 128];  // Bs[k][n]

    const int bm = blockIdx.y * 128;
    const int bn = blockIdx.x * 128;
    const int tid = threadIdx.x;
    const int tx = tid & 15;
    const int ty = tid >> 4;

    float acc[8][8];
#pragma unroll
    for (int i = 0; i < 8; i++)
#pragma unroll
        for (int j = 0; j < 8; j++) acc[i][j] = 0.f;

    for (int k0 = 0; k0 < DIM; k0 += 16) {
        // A tile: 128 rows x 16 k, via float4 (512 float4, 2 per thread)
#pragma unroll
        for (int u = 0; u < 2; u++) {
            int i = tid + u * 256;
            int r = i >> 2;
            int kq = (i & 3) * 4;
            float4 v = *(const float4*)(A + (size_t)(bm + r) * DIM + k0 + kq);
            As[(kq + 0) * 132 + r] = v.x;
            As[(kq + 1) * 132 + r] = v.y;
            As[(kq + 2) * 132 + r] = v.z;
            As[(kq + 3) * 132 + r] = v.w;
        }
        // B tile: 16 k x 128 n, via float4, fully coalesced
#pragma unroll
        for (int u = 0; u < 2; u++) {
            int i = tid + u * 256;
            int k = i >> 5;
            int nq = (i & 31) * 4;
            *(float4*)(Bs + k * 128 + nq) =
                *(const float4*)(W + (size_t)(k0 + k) * DIM + bn + nq);
        }
        __syncthreads();

#pragma unroll
        for (int kk = 0; kk < 16; kk++) {
            float4 a0 = *(const float4*)(As + kk * 132 + ty * 8);
            float4 a1 = *(const float4*)(As + kk * 132 + ty * 8 + 4);
            float4 b0 = *(const float4*)(Bs + kk * 128 + tx * 8);
            float4 b1 = *(const float4*)(Bs + kk * 128 + tx * 8 + 4);
            float a[8] = {a0.x, a0.y, a0.z, a0.w, a1.x, a1.y, a1.z, a1.w};
            float b[8] = {b0.x, b0.y, b0.z, b0.w, b1.x, b1.y, b1.z, b1.w};
#pragma unroll
            for (int i = 0; i < 8; i++)
#pragma unroll
                for (int j = 0; j < 8; j++) acc[i][j] += a[i] * b[j];
        }
        __syncthreads();
    }

#pragma unroll
    for (int i = 0; i < 8; i++) {
        size_t row = (size_t)(bm + ty * 8 + i) * DIM + bn;
#pragma unroll
        for (int j = 0; j < 8; j++) {
            C[row + tx * 8 + j] = acc[i][j] + bias[bn + tx * 8 + j];
        }
    }
}

// ---------------- RMSNorm over last dim (1536), times gain; in place ----------------
__global__ __launch_bounds__(256) void rmsnorm_kernel(
    float* __restrict__ x, const float* __restrict__ g)
{
    const int row = blockIdx.x;
    float* xr = x + (size_t)row * DIM;
    const int tid = threadIdx.x;

    float ss = 0.f;
    for (int i = tid; i < DIM; i += 256) {
        float v = xr[i];
        ss += v * v;
    }
#pragma unroll
    for (int off = 16; off; off >>= 1) ss += __shfl_xor_sync(0xffffffffu, ss, off);

    __shared__ float wsum[8];
    __shared__ float inv_s;
    if ((tid & 31) == 0) wsum[tid >> 5] = ss;
    __syncthreads();
    if (tid == 0) {
        float t = 0.f;
#pragma unroll
        for (int w = 0; w < 8; w++) t += wsum[w];
        inv_s = rsqrtf(t / (float)DIM + 1e-6f);
    }
    __syncthreads();
    float inv = inv_s;
    for (int i = tid; i < DIM; i += 256) {
        xr[i] = xr[i] * inv * g[i];
    }
}

// ---------------- RoPE: per (t, head, pair) ----------------
// out[t, h*128+2i]   = e*c - o*s ; out[t, h*128+2i+1] = e*s + o*c ; c,s indexed (t, i), i<64
__global__ __launch_bounds__(256) void rope_kernel(
    const float* __restrict__ in, float* __restrict__ out,
    const float* __restrict__ rc, const float* __restrict__ rs)
{
    int idx = blockIdx.x * 256 + threadIdx.x;  // T_LEN * 768 pairs
    if (idx >= T_LEN * (DIM / 2)) return;
    int t = idx / (DIM / 2);
    int p = idx % (DIM / 2);
    int h = p >> 6;       // p / 64
    int i = p & 63;       // p % 64
    size_t base = (size_t)t * DIM + h * DH + 2 * i;
    float e = in[base];
    float o = in[base + 1];
    float c = rc[t * (DH / 2) + i];
    float s = rs[t * (DH / 2) + i];
    out[base]     = e * c - o * s;
    out[base + 1] = e * s + o * c;
}

// ---------------- Flash attention (fp32): 64 queries x 64 keys tiles, DH=128 ----------------
// grid = (T_LEN/64, NH). Q,K,V in flat (rows, DIM) layout, head h at cols [h*128, h*128+128).
// Out[(t, h*128+d)] = softmax(QK^T/sqrt(128)) V ; accumulate=1 adds into Out.
#define ATTN_SMEM_BYTES (29440 * 4)

__global__ __launch_bounds__(256) void attn_kernel(
    const float* __restrict__ Q, const float* __restrict__ Kp,
    const float* __restrict__ Vp, float* __restrict__ Out,
    int Tk, int accumulate)
{
    extern __shared__ float sm[];
    float* Qt  = sm;           // [128][65]  Qt[c*65 + r] = Q[q0+r, h*128+c]
    float* Kt  = sm + 8320;    // [128][65]
    float* Vs  = sm + 16640;   // [64][132]  Vs[r*132 + c]
    float* Ps  = sm + 25088;   // [64][66]
    float* m_s = sm + 29312;   // [64]
    float* l_s = sm + 29376;   // [64]

    const int h  = blockIdx.y;
    const int q0 = blockIdx.x * 64;
    const int tid = threadIdx.x;
    const int tx = tid & 15;
    const int ty = tid >> 4;
    const float scale = 0.08838834764831845f;  // 1/sqrt(128)

    for (int i = tid; i < 64 * 128; i += 256) {
        int r = i >> 7, c = i & 127;
        Qt[c * 65 + r] = Q[(size_t)(q0 + r) * DIM + h * DH + c];
    }
    if (tid < 64) { m_s[tid] = -1e30f; l_s[tid] = 0.f; }
    __syncthreads();

    float o[4][8];
#pragma unroll
    for (int i = 0; i < 4; i++)
#pragma unroll
        for (int j = 0; j < 8; j++) o[i][j] = 0.f;

    for (int k0 = 0; k0 < Tk; k0 += 64) {
        for (int i = tid; i < 64 * 128; i += 256) {
            int r = i >> 7, c = i & 127;
            float kv = Kp[(size_t)(k0 + r) * DIM + h * DH + c];
            float vv = Vp[(size_t)(k0 + r) * DIM + h * DH + c];
            Kt[c * 65 + r]  = kv;
            Vs[r * 132 + c] = vv;
        }
        __syncthreads();

        // S = Q K^T, 4x4 per thread: rows 4ty..+3, cols 4tx..+3
        float s[4][4];
#pragma unroll
        for (int i = 0; i < 4; i++)
#pragma unroll
            for (int j = 0; j < 4; j++) s[i][j] = 0.f;

#pragma unroll 8
        for (int kk = 0; kk < 128; kk++) {
            float qv[4], kv[4];
#pragma unroll
            for (int i = 0; i < 4; i++) qv[i] = Qt[kk * 65 + ty * 4 + i];
#pragma unroll
            for (int j = 0; j < 4; j++) kv[j] = Kt[kk * 65 + tx * 4 + j];
#pragma unroll
            for (int i = 0; i < 4; i++)
#pragma unroll
                for (int j = 0; j < 4; j++) s[i][j] += qv[i] * kv[j];
        }

        // Online softmax per row (row owned by the 16 tx-lanes of one warp half)
#pragma unroll
        for (int i = 0; i < 4; i++) {
            int r = ty * 4 + i;
            float rm = -1e30f;
#pragma unroll
            for (int j = 0; j < 4; j++) {
                s[i][j] *= scale;
                rm = fmaxf(rm, s[i][j]);
            }
#pragma unroll
            for (int off = 8; off; off >>= 1)
                rm = fmaxf(rm, __shfl_xor_sync(0xffffffffu, rm, off));
            float mold = m_s[r];
            float mnew = fmaxf(mold, rm);
            float alpha = __expf(mold - mnew);
            float psum = 0.f;
#pragma unroll
            for (int j = 0; j < 4; j++) {
                float p = __expf(s[i][j] - mnew);
                Ps[r * 66 + tx * 4 + j] = p;
                psum += p;
            }
#pragma unroll
            for (int off = 8; off; off >>= 1)
                psum += __shfl_xor_sync(0xffffffffu, psum, off);
            if (tx == 0) {
                m_s[r] = mnew;
                l_s[r] = l_s[r] * alpha + psum;
            }
#pragma unroll
            for (int j = 0; j < 8; j++) o[i][j] *= alpha;
        }
        __syncwarp();  // Ps rows needed below are produced within this warp

        // O += P @ V : thread owns rows 4ty..+3, cols 8tx..+7
#pragma unroll 4
        for (int kk = 0; kk < 64; kk++) {
            float pr[4];
#pragma unroll
            for (int i = 0; i < 4; i++) pr[i] = Ps[(ty * 4 + i) * 66 + kk];
            float4 v0 = *(const float4*)(Vs + kk * 132 + tx * 8);
            float4 v1 = *(const float4*)(Vs + kk * 132 + tx * 8 + 4);
            float vv[8] = {v0.x, v0.y, v0.z, v0.w, v1.x, v1.y, v1.z, v1.w};
#pragma unroll
            for (int i = 0; i < 4; i++)
#pragma unroll
                for (int j = 0; j < 8; j++) o[i][j] += pr[i] * vv[j];
        }
        __syncthreads();  // before reloading K/V tiles
    }

#pragma unroll
    for (int i = 0; i < 4; i++) {
        float inv = 1.f / l_s[ty * 4 + i];
        size_t base = (size_t)(q0 + ty * 4 + i) * DIM + h * DH + tx * 8;
#pragma unroll
        for (int j = 0; j < 8; j++) {
            float val = o[i][j] * inv;
            if (accumulate) Out[base + j] += val;
            else            Out[base + j] = val;
        }
    }
}

// ---------------- launch ----------------
extern "C" void kernel_launch(void* const* d_in, const int* in_sizes, int n_in,
                              void* d_out, int out_size)
{
    const float* hs   = (const float*)d_in[0];
    const float* rhs  = (const float*)d_in[1];
    const float* rcos = (const float*)d_in[2];
    const float* rsin = (const float*)d_in[3];
    const float* Wq   = (const float*)d_in[4];
    const float* bq   = (const float*)d_in[5];
    const float* Wk   = (const float*)d_in[6];
    const float* bk   = (const float*)d_in[7];
    const float* Wv   = (const float*)d_in[8];
    const float* bv   = (const float*)d_in[9];
    const float* Wkr  = (const float*)d_in[10];
    const float* bkr  = (const float*)d_in[11];
    const float* Wvr  = (const float*)d_in[12];
    const float* bvr  = (const float*)d_in[13];
    const float* Wo   = (const float*)d_in[14];
    const float* bo   = (const float*)d_in[15];
    const float* gq   = (const float*)d_in[16];
    const float* gk   = (const float*)d_in[17];
    float* out = (float*)d_out;

    float *qlin, *klin, *vlin, *krlin, *vrlin, *qrope, *attn;
    cudaGetSymbolAddress((void**)&qlin,  g_qlin);
    cudaGetSymbolAddress((void**)&klin,  g_klin);
    cudaGetSymbolAddress((void**)&vlin,  g_vlin);
    cudaGetSymbolAddress((void**)&krlin, g_krlin);
    cudaGetSymbolAddress((void**)&vrlin, g_vrlin);
    cudaGetSymbolAddress((void**)&qrope, g_qrope);
    cudaGetSymbolAddress((void**)&attn,  g_attn);

    cudaFuncSetAttribute(attn_kernel,
                         cudaFuncAttributeMaxDynamicSharedMemorySize,
                         ATTN_SMEM_BYTES);

    dim3 gemm_grid_main(DIM / 128, T_LEN / 128);   // (12, 32)
    dim3 gemm_grid_ref(DIM / 128, TR_LEN / 128);   // (12, 8)

    // Projections
    gemm_bias_kernel<<<gemm_grid_main, 256>>>(hs,  Wq,  bq,  qlin);
    gemm_bias_kernel<<<gemm_grid_main, 256>>>(hs,  Wk,  bk,  klin);
    gemm_bias_kernel<<<gemm_grid_main, 256>>>(hs,  Wv,  bv,  vlin);
    gemm_bias_kernel<<<gemm_grid_ref,  256>>>(rhs, Wkr, bkr, krlin);
    gemm_bias_kernel<<<gemm_grid_ref,  256>>>(rhs, Wvr, bvr, vrlin);

    // RMSNorms (in place)
    rmsnorm_kernel<<<T_LEN, 256>>>(qlin,  gq);
    rmsnorm_kernel<<<T_LEN, 256>>>(klin,  gk);
    rmsnorm_kernel<<<TR_LEN, 256>>>(krlin, gk);

    // RoPE: q out-of-place (unroped q needed for ref attn), k in place
    int rope_blocks = (T_LEN * (DIM / 2) + 255) / 256;
    rope_kernel<<<rope_blocks, 256>>>(qlin, qrope, rcos, rsin);
    rope_kernel<<<rope_blocks, 256>>>(klin, klin,  rcos, rsin);

    // Attention: ref writes, main accumulates
    dim3 attn_grid(T_LEN / 64, NH);  // (64, 12)
    attn_kernel<<<attn_grid, 256, ATTN_SMEM_BYTES>>>(qlin,  krlin, vrlin, attn, TR_LEN, 0);
    attn_kernel<<<attn_grid, 256, ATTN_SMEM_BYTES>>>(qrope, klin,  vlin,  attn, T_LEN, 1);

    // Output projection
    gemm_bias_kernel<<<gemm_grid_main, 256>>>(attn, Wo, bo, out);
}

// round 3
// speedup vs baseline: 4.0816x; 4.0816x over previous
#include <cuda_runtime.h>
#include <cuda_bf16.h>
#include <math.h>

#define T_LEN 4096
#define TR_LEN 1024
#define DIM 1536
#define NH 12
#define DH 128

// ---------------- scratch (device globals; no allocation allowed) ----------------
__device__ float g_qlin[T_LEN * DIM];   // q_lin -> rmsnorm(q) in place
__device__ float g_klin[T_LEN * DIM];   // k_lin -> rmsnorm(k) -> rope(k) in place
__device__ float g_vlin[T_LEN * DIM];   // v
__device__ float g_krlin[TR_LEN * DIM]; // ref k_lin -> rmsnorm in place
__device__ float g_vrlin[TR_LEN * DIM]; // ref v
__device__ float g_qrope[T_LEN * DIM];  // rope(q) out of place
__device__ float g_attn[T_LEN * DIM];   // main_out + ref_out accumulator

// ---------------- small PTX helpers ----------------
__device__ __forceinline__ unsigned f2tf(float f) {
    unsigned u;
    asm("cvt.rna.tf32.f32 %0, %1;" : "=r"(u) : "f"(f));
    return u;
}
__device__ __forceinline__ void mma_tf32(float& c0, float& c1, float& c2, float& c3,
                                         unsigned a0, unsigned a1, unsigned a2, unsigned a3,
                                         unsigned b0, unsigned b1) {
    asm volatile(
        "mma.sync.aligned.m16n8k8.row.col.f32.tf32.tf32.f32 "
        "{%0,%1,%2,%3},{%4,%5,%6,%7},{%8,%9},{%0,%1,%2,%3};"
        : "+f"(c0), "+f"(c1), "+f"(c2), "+f"(c3)
        : "r"(a0), "r"(a1), "r"(a2), "r"(a3), "r"(b0), "r"(b1));
}
__device__ __forceinline__ void cp16(void* dst_smem, const void* src) {
    unsigned s = (unsigned)__cvta_generic_to_shared(dst_smem);
    asm volatile("cp.async.cg.shared.global [%0], [%1], 16;" :: "r"(s), "l"(src));
}
__device__ __forceinline__ void cp_commit() { asm volatile("cp.async.commit_group;"); }
__device__ __forceinline__ void cp_wait1()  { asm volatile("cp.async.wait_group 1;"); }
__device__ __forceinline__ void cp_wait0()  { asm volatile("cp.async.wait_group 0;"); }

// ================= GEMM (tf32 tensor cores): C[Mx1536] = A @ W + bias =================
// 128x128 tile, ktile=32, 256 threads (2x4 warps, 64x32 per warp), cp.async double buffer.
#define G_APITCH 36
#define G_BPITCH 136
#define G_OFF_A0 0
#define G_OFF_A1 (128 * G_APITCH)
#define G_OFF_B0 (2 * 128 * G_APITCH)
#define G_OFF_B1 (G_OFF_B0 + 32 * G_BPITCH)
#define GEMM_SMEM_BYTES ((G_OFF_B1 + 32 * G_BPITCH) * 4)

__global__ __launch_bounds__(256) void gemm_tc(
    const float* __restrict__ A, const float* __restrict__ W,
    const float* __restrict__ bias, float* __restrict__ C)
{
    extern __shared__ float smf[];
    const int bm = blockIdx.y * 128;
    const int bn = blockIdx.x * 128;
    const int tid = threadIdx.x;
    const int lane = tid & 31, warp = tid >> 5;
    const int g = lane >> 2, l = lane & 3;
    const int wm = (warp >> 2) * 64;
    const int wn = (warp & 3) * 32;

    float c[4][4][4];
#pragma unroll
    for (int mt = 0; mt < 4; mt++)
#pragma unroll
        for (int nt = 0; nt < 4; nt++)
#pragma unroll
            for (int i = 0; i < 4; i++) c[mt][nt][i] = 0.f;

    auto issue = [&](int kt, int buf) {
        float* Ad = smf + (buf ? G_OFF_A1 : G_OFF_A0);
        float* Bd = smf + (buf ? G_OFF_B1 : G_OFF_B0);
        const int k0 = kt * 32;
#pragma unroll
        for (int u = 0; u < 4; u++) {
            int i = tid + u * 256;              // 1024 float4 for A
            int r = i >> 3, c4 = i & 7;
            cp16(Ad + r * G_APITCH + c4 * 4,
                 A + (size_t)(bm + r) * DIM + k0 + c4 * 4);
        }
#pragma unroll
        for (int u = 0; u < 4; u++) {
            int i = tid + u * 256;              // 1024 float4 for B
            int k = i >> 5, n4 = i & 31;
            cp16(Bd + k * G_BPITCH + n4 * 4,
                 W + (size_t)(k0 + k) * DIM + bn + n4 * 4);
        }
        cp_commit();
    };

    issue(0, 0);
    const int NKT = DIM / 32;  // 48
    for (int kt = 0; kt < NKT; kt++) {
        int buf = kt & 1;
        if (kt + 1 < NKT) { issue(kt + 1, buf ^ 1); cp_wait1(); }
        else              { cp_wait0(); }
        __syncthreads();

        const float* As = smf + (buf ? G_OFF_A1 : G_OFF_A0);
        const float* Bs = smf + (buf ? G_OFF_B1 : G_OFF_B0);

#pragma unroll
        for (int kk = 0; kk < 4; kk++) {
            unsigned a[4][4];
#pragma unroll
            for (int mt = 0; mt < 4; mt++) {
                int row = wm + mt * 16;
                a[mt][0] = f2tf(As[(row + g)     * G_APITCH + kk * 8 + l]);
                a[mt][1] = f2tf(As[(row + g + 8) * G_APITCH + kk * 8 + l]);
                a[mt][2] = f2tf(As[(row + g)     * G_APITCH + kk * 8 + l + 4]);
                a[mt][3] = f2tf(As[(row + g + 8) * G_APITCH + kk * 8 + l + 4]);
            }
            unsigned b[4][2];
#pragma unroll
            for (int nt = 0; nt < 4; nt++) {
                int col = wn + nt * 8;
                b[nt][0] = f2tf(Bs[(kk * 8 + l)     * G_BPITCH + col + g]);
                b[nt][1] = f2tf(Bs[(kk * 8 + l + 4) * G_BPITCH + col + g]);
            }
#pragma unroll
            for (int mt = 0; mt < 4; mt++)
#pragma unroll
                for (int nt = 0; nt < 4; nt++)
                    mma_tf32(c[mt][nt][0], c[mt][nt][1], c[mt][nt][2], c[mt][nt][3],
                             a[mt][0], a[mt][1], a[mt][2], a[mt][3],
                             b[nt][0], b[nt][1]);
        }
        __syncthreads();
    }

#pragma unroll
    for (int mt = 0; mt < 4; mt++) {
#pragma unroll
        for (int nt = 0; nt < 4; nt++) {
            int row = bm + wm + mt * 16 + g;
            int col = bn + wn + nt * 8 + 2 * l;
            float b0 = bias[col], b1 = bias[col + 1];
            C[(size_t)row * DIM + col]           = c[mt][nt][0] + b0;
            C[(size_t)row * DIM + col + 1]       = c[mt][nt][1] + b1;
            C[(size_t)(row + 8) * DIM + col]     = c[mt][nt][2] + b0;
            C[(size_t)(row + 8) * DIM + col + 1] = c[mt][nt][3] + b1;
        }
    }
}

// ---------------- RMSNorm over last dim (1536), times gain; in place ----------------
__global__ __launch_bounds__(256) void rmsnorm_kernel(
    float* __restrict__ x, const float* __restrict__ g)
{
    const int row = blockIdx.x;
    float* xr = x + (size_t)row * DIM;
    const int tid = threadIdx.x;

    float ss = 0.f;
    for (int i = tid; i < DIM; i += 256) {
        float v = xr[i];
        ss += v * v;
    }
#pragma unroll
    for (int off = 16; off; off >>= 1) ss += __shfl_xor_sync(0xffffffffu, ss, off);

    __shared__ float wsum[8];
    __shared__ float inv_s;
    if ((tid & 31) == 0) wsum[tid >> 5] = ss;
    __syncthreads();
    if (tid == 0) {
        float t = 0.f;
#pragma unroll
        for (int w = 0; w < 8; w++) t += wsum[w];
        inv_s = rsqrtf(t / (float)DIM + 1e-6f);
    }
    __syncthreads();
    float inv = inv_s;
    for (int i = tid; i < DIM; i += 256) {
        xr[i] = xr[i] * inv * g[i];
    }
}

// ---------------- RoPE ----------------
__global__ __launch_bounds__(256) void rope_kernel(
    const float* __restrict__ in, float* __restrict__ out,
    const float* __restrict__ rc, const float* __restrict__ rs)
{
    int idx = blockIdx.x * 256 + threadIdx.x;
    if (idx >= T_LEN * (DIM / 2)) return;
    int t = idx / (DIM / 2);
    int p = idx % (DIM / 2);
    int h = p >> 6;
    int i = p & 63;
    size_t base = (size_t)t * DIM + h * DH + 2 * i;
    float e = in[base];
    float o = in[base + 1];
    float c = rc[t * (DH / 2) + i];
    float s = rs[t * (DH / 2) + i];
    out[base]     = e * c - o * s;
    out[base + 1] = e * s + o * c;
}

// ================= Flash attention (tf32 tensor cores) =================
// grid = (T_LEN/64, NH), 128 threads (4 warps). Warp w owns query rows [q0+16w, +16).
// KV tiles of 64 keys, double buffered via cp.async.
#define AT_QPITCH 132
#define AT_KPITCH 132
#define AT_VPITCH 136
#define AT_PPITCH 68
#define AT_OFF_Q  0
#define AT_OFF_K0 (64 * AT_QPITCH)
#define AT_OFF_K1 (AT_OFF_K0 + 64 * AT_KPITCH)
#define AT_OFF_V0 (AT_OFF_K1 + 64 * AT_KPITCH)
#define AT_OFF_V1 (AT_OFF_V0 + 64 * AT_VPITCH)
#define AT_OFF_P  (AT_OFF_V1 + 64 * AT_VPITCH)
#define ATTN_SMEM_BYTES ((AT_OFF_P + 4 * 16 * AT_PPITCH) * 4)

__global__ __launch_bounds__(128) void attn_tc(
    const float* __restrict__ Q, const float* __restrict__ Kp,
    const float* __restrict__ Vp, float* __restrict__ Out,
    int Tk, int accumulate)
{
    extern __shared__ float smf[];
    unsigned* smu = (unsigned*)smf;

    const int h = blockIdx.y;
    const int q0 = blockIdx.x * 64;
    const int tid = threadIdx.x;
    const int lane = tid & 31, warp = tid >> 5;
    const int g = lane >> 2, l = lane & 3;
    const float scale = 0.08838834764831845f;  // 1/sqrt(128)

    auto issue_tile = [&](int t, int buf) {
        float* Kd = smf + (buf ? AT_OFF_K1 : AT_OFF_K0);
        float* Vd = smf + (buf ? AT_OFF_V1 : AT_OFF_V0);
        const size_t rowbase = (size_t)(t * 64) * DIM + h * DH;
#pragma unroll
        for (int u = 0; u < 16; u++) {
            int i = tid + u * 128;              // 2048 float4 for K
            int r = i >> 5, c4 = i & 31;
            cp16(Kd + r * AT_KPITCH + c4 * 4, Kp + rowbase + (size_t)r * DIM + c4 * 4);
        }
#pragma unroll
        for (int u = 0; u < 16; u++) {
            int i = tid + u * 128;              // 2048 float4 for V
            int r = i >> 5, c4 = i & 31;
            cp16(Vd + r * AT_VPITCH + c4 * 4, Vp + rowbase + (size_t)r * DIM + c4 * 4);
        }
        cp_commit();
    };

    issue_tile(0, 0);

    // Q tile: scale + convert to tf32 bits in smem
    for (int u = 0; u < 16; u++) {
        int i = tid + u * 128;
        int r = i >> 5, c4 = i & 31;
        float4 v = *(const float4*)(Q + (size_t)(q0 + r) * DIM + h * DH + c4 * 4);
        unsigned* d = smu + AT_OFF_Q + r * AT_QPITCH + c4 * 4;
        d[0] = f2tf(v.x * scale);
        d[1] = f2tf(v.y * scale);
        d[2] = f2tf(v.z * scale);
        d[3] = f2tf(v.w * scale);
    }

    float o[16][4];
#pragma unroll
    for (int nt = 0; nt < 16; nt++)
#pragma unroll
        for (int i = 0; i < 4; i++) o[nt][i] = 0.f;
    float m0 = -1e30f, m1 = -1e30f, l0 = 0.f, l1 = 0.f;

    const int qrow = warp * 16;
    const int pbase = AT_OFF_P + warp * 16 * AT_PPITCH;
    const int ntiles = Tk / 64;

    for (int t = 0; t < ntiles; t++) {
        int buf = t & 1;
        if (t + 1 < ntiles) { issue_tile(t + 1, buf ^ 1); cp_wait1(); }
        else                { cp_wait0(); }
        __syncthreads();

        const float* Ks = smf + (buf ? AT_OFF_K1 : AT_OFF_K0);
        const float* Vs = smf + (buf ? AT_OFF_V1 : AT_OFF_V0);

        // ---- S = (Q*scale) K^T ----
        float s[8][4];
#pragma unroll
        for (int nt = 0; nt < 8; nt++)
#pragma unroll
            for (int i = 0; i < 4; i++) s[nt][i] = 0.f;

#pragma unroll
        for (int kk = 0; kk < 16; kk++) {
            unsigned a0 = smu[AT_OFF_Q + (qrow + g)     * AT_QPITCH + kk * 8 + l];
            unsigned a1 = smu[AT_OFF_Q + (qrow + g + 8) * AT_QPITCH + kk * 8 + l];
            unsigned a2 = smu[AT_OFF_Q + (qrow + g)     * AT_QPITCH + kk * 8 + l + 4];
            unsigned a3 = smu[AT_OFF_Q + (qrow + g + 8) * AT_QPITCH + kk * 8 + l + 4];
#pragma unroll
            for (int nt = 0; nt < 8; nt++) {
                unsigned b0 = f2tf(Ks[(nt * 8 + g) * AT_KPITCH + kk * 8 + l]);
                unsigned b1 = f2tf(Ks[(nt * 8 + g) * AT_KPITCH + kk * 8 + l + 4]);
                mma_tf32(s[nt][0], s[nt][1], s[nt][2], s[nt][3], a0, a1, a2, a3, b0, b1);
            }
        }

        // ---- online softmax (rows are warp-local; quad = 4 lanes of one row) ----
        float tm0 = -1e30f, tm1 = -1e30f;
#pragma unroll
        for (int nt = 0; nt < 8; nt++) {
            tm0 = fmaxf(tm0, fmaxf(s[nt][0], s[nt][1]));
            tm1 = fmaxf(tm1, fmaxf(s[nt][2], s[nt][3]));
        }
        tm0 = fmaxf(tm0, __shfl_xor_sync(0xffffffffu, tm0, 1));
        tm0 = fmaxf(tm0, __shfl_xor_sync(0xffffffffu, tm0, 2));
        tm1 = fmaxf(tm1, __shfl_xor_sync(0xffffffffu, tm1, 1));
        tm1 = fmaxf(tm1, __shfl_xor_sync(0xffffffffu, tm1, 2));
        float mn0 = fmaxf(m0, tm0), mn1 = fmaxf(m1, tm1);
        float al0 = __expf(m0 - mn0), al1 = __expf(m1 - mn1);
        m0 = mn0; m1 = mn1;

        float sum0 = 0.f, sum1 = 0.f;
#pragma unroll
        for (int nt = 0; nt < 8; nt++) {
            float p0 = __expf(s[nt][0] - mn0);
            float p1 = __expf(s[nt][1] - mn0);
            float p2 = __expf(s[nt][2] - mn1);
            float p3 = __expf(s[nt][3] - mn1);
            sum0 += p0 + p1;
            sum1 += p2 + p3;
            unsigned* d0 = smu + pbase + g * AT_PPITCH + nt * 8 + 2 * l;
            unsigned* d1 = smu + pbase + (g + 8) * AT_PPITCH + nt * 8 + 2 * l;
            d0[0] = f2tf(p0); d0[1] = f2tf(p1);
            d1[0] = f2tf(p2); d1[1] = f2tf(p3);
        }
        sum0 += __shfl_xor_sync(0xffffffffu, sum0, 1);
        sum0 += __shfl_xor_sync(0xffffffffu, sum0, 2);
        sum1 += __shfl_xor_sync(0xffffffffu, sum1, 1);
        sum1 += __shfl_xor_sync(0xffffffffu, sum1, 2);
        l0 = l0 * al0 + sum0;
        l1 = l1 * al1 + sum1;
#pragma unroll
        for (int nt = 0; nt < 16; nt++) {
            o[nt][0] *= al0; o[nt][1] *= al0;
            o[nt][2] *= al1; o[nt][3] *= al1;
        }
        __syncwarp();

        // ---- O += P @ V ----
#pragma unroll
        for (int kt = 0; kt < 8; kt++) {
            unsigned a0 = smu[pbase + g * AT_PPITCH + kt * 8 + l];
            unsigned a1 = smu[pbase + (g + 8) * AT_PPITCH + kt * 8 + l];
            unsigned a2 = smu[pbase + g * AT_PPITCH + kt * 8 + l + 4];
            unsigned a3 = smu[pbase + (g + 8) * AT_PPITCH + kt * 8 + l + 4];
#pragma unroll
            for (int nt = 0; nt < 16; nt++) {
                unsigned b0 = f2tf(Vs[(kt * 8 + l)     * AT_VPITCH + nt * 8 + g]);
                unsigned b1 = f2tf(Vs[(kt * 8 + l + 4) * AT_VPITCH + nt * 8 + g]);
                mma_tf32(o[nt][0], o[nt][1], o[nt][2], o[nt][3], a0, a1, a2, a3, b0, b1);
            }
        }
        __syncthreads();
    }

    // ---- epilogue ----
    float inv0 = 1.f / l0, inv1 = 1.f / l1;
    int row0 = q0 + warp * 16 + g;
    int row1 = row0 + 8;
    if (accumulate) {
#pragma unroll
        for (int nt = 0; nt < 16; nt++) {
            int col = h * DH + nt * 8 + 2 * l;
            size_t i0 = (size_t)row0 * DIM + col;
            size_t i1 = (size_t)row1 * DIM + col;
            Out[i0]     += o[nt][0] * inv0;
            Out[i0 + 1] += o[nt][1] * inv0;
            Out[i1]     += o[nt][2] * inv1;
            Out[i1 + 1] += o[nt][3] * inv1;
        }
    } else {
#pragma unroll
        for (int nt = 0; nt < 16; nt++) {
            int col = h * DH + nt * 8 + 2 * l;
            size_t i0 = (size_t)row0 * DIM + col;
            size_t i1 = (size_t)row1 * DIM + col;
            Out[i0]     = o[nt][0] * inv0;
            Out[i0 + 1] = o[nt][1] * inv0;
            Out[i1]     = o[nt][2] * inv1;
            Out[i1 + 1] = o[nt][3] * inv1;
        }
    }
}

// ---------------- launch ----------------
extern "C" void kernel_launch(void* const* d_in, const int* in_sizes, int n_in,
                              void* d_out, int out_size)
{
    const float* hs   = (const float*)d_in[0];
    const float* rhs  = (const float*)d_in[1];
    const float* rcos = (const float*)d_in[2];
    const float* rsin = (const float*)d_in[3];
    const float* Wq   = (const float*)d_in[4];
    const float* bq   = (const float*)d_in[5];
    const float* Wk   = (const float*)d_in[6];
    const float* bk   = (const float*)d_in[7];
    const float* Wv   = (const float*)d_in[8];
    const float* bv   = (const float*)d_in[9];
    const float* Wkr  = (const float*)d_in[10];
    const float* bkr  = (const float*)d_in[11];
    const float* Wvr  = (const float*)d_in[12];
    const float* bvr  = (const float*)d_in[13];
    const float* Wo   = (const float*)d_in[14];
    const float* bo   = (const float*)d_in[15];
    const float* gq   = (const float*)d_in[16];
    const float* gk   = (const float*)d_in[17];
    float* out = (float*)d_out;

    float *qlin, *klin, *vlin, *krlin, *vrlin, *qrope, *attn;
    cudaGetSymbolAddress((void**)&qlin,  g_qlin);
    cudaGetSymbolAddress((void**)&klin,  g_klin);
    cudaGetSymbolAddress((void**)&vlin,  g_vlin);
    cudaGetSymbolAddress((void**)&krlin, g_krlin);
    cudaGetSymbolAddress((void**)&vrlin, g_vrlin);
    cudaGetSymbolAddress((void**)&qrope, g_qrope);
    cudaGetSymbolAddress((void**)&attn,  g_attn);

    cudaFuncSetAttribute(gemm_tc,
                         cudaFuncAttributeMaxDynamicSharedMemorySize, GEMM_SMEM_BYTES);
    cudaFuncSetAttribute(attn_tc,
                         cudaFuncAttributeMaxDynamicSharedMemorySize, ATTN_SMEM_BYTES);

    dim3 gemm_grid_main(DIM / 128, T_LEN / 128);   // (12, 32)
    dim3 gemm_grid_ref(DIM / 128, TR_LEN / 128);   // (12, 8)

    // Projections (tf32 tensor cores)
    gemm_tc<<<gemm_grid_main, 256, GEMM_SMEM_BYTES>>>(hs,  Wq,  bq,  qlin);
    gemm_tc<<<gemm_grid_main, 256, GEMM_SMEM_BYTES>>>(hs,  Wk,  bk,  klin);
    gemm_tc<<<gemm_grid_main, 256, GEMM_SMEM_BYTES>>>(hs,  Wv,  bv,  vlin);
    gemm_tc<<<gemm_grid_ref,  256, GEMM_SMEM_BYTES>>>(rhs, Wkr, bkr, krlin);
    gemm_tc<<<gemm_grid_ref,  256, GEMM_SMEM_BYTES>>>(rhs, Wvr, bvr, vrlin);

    // RMSNorms (in place)
    rmsnorm_kernel<<<T_LEN, 256>>>(qlin,  gq);
    rmsnorm_kernel<<<T_LEN, 256>>>(klin,  gk);
    rmsnorm_kernel<<<TR_LEN, 256>>>(krlin, gk);

    // RoPE: q out-of-place (unroped q needed for ref attn), k in place
    int rope_blocks = (T_LEN * (DIM / 2) + 255) / 256;
    rope_kernel<<<rope_blocks, 256>>>(qlin, qrope, rcos, rsin);
    rope_kernel<<<rope_blocks, 256>>>(klin, klin,  rcos, rsin);

    // Attention: ref writes, main accumulates
    dim3 attn_grid(T_LEN / 64, NH);  // (64, 12)
    attn_tc<<<attn_grid, 128, ATTN_SMEM_BYTES>>>(qlin,  krlin, vrlin, attn, TR_LEN, 0);
    attn_tc<<<attn_grid, 128, ATTN_SMEM_BYTES>>>(qrope, klin,  vlin,  attn, T_LEN, 1);

    // Output projection
    gemm_tc<<<gemm_grid_main, 256, GEMM_SMEM_BYTES>>>(attn, Wo, bo, out);
}

// round 4
// speedup vs baseline: 5.0198x; 1.2299x over previous
#include <cuda_runtime.h>
#include <cuda_bf16.h>
#include <math.h>

#define T_LEN 4096
#define TR_LEN 1024
#define DIM 1536
#define NH 12
#define DH 128

// ---------------- scratch (device globals; no allocation allowed) ----------------
__device__ float g_qlin[T_LEN * DIM];
__device__ float g_klin[T_LEN * DIM];
__device__ float g_vlin[T_LEN * DIM];
__device__ float g_krlin[TR_LEN * DIM];
__device__ float g_vrlin[TR_LEN * DIM];
__device__ float g_attn[T_LEN * DIM];

// tf32 bit-pattern buffers
__device__ unsigned g_hsb[T_LEN * DIM];
__device__ unsigned g_rhsb[TR_LEN * DIM];
__device__ unsigned g_wb[6 * DIM * DIM];     // Wq, Wk, Wv, Wkr, Wvr, Wo
__device__ unsigned g_qtfb[T_LEN * DIM];     // rms(q)*scale (ref-attn Q)
__device__ unsigned g_qropeb[T_LEN * DIM];   // rope(rms(q))*scale (main-attn Q)
__device__ unsigned g_kb[T_LEN * DIM];       // rope(rms(k))
__device__ unsigned g_vb[T_LEN * DIM];
__device__ unsigned g_krb[TR_LEN * DIM];     // rms(ref k)
__device__ unsigned g_vrb[TR_LEN * DIM];
__device__ unsigned g_attnb[T_LEN * DIM];

// ---------------- small PTX helpers ----------------
__device__ __forceinline__ unsigned f2tf(float f) {
    unsigned u;
    asm("cvt.rna.tf32.f32 %0, %1;" : "=r"(u) : "f"(f));
    return u;
}
__device__ __forceinline__ void mma_tf32(float& c0, float& c1, float& c2, float& c3,
                                         unsigned a0, unsigned a1, unsigned a2, unsigned a3,
                                         unsigned b0, unsigned b1) {
    asm volatile(
        "mma.sync.aligned.m16n8k8.row.col.f32.tf32.tf32.f32 "
        "{%0,%1,%2,%3},{%4,%5,%6,%7},{%8,%9},{%0,%1,%2,%3};"
        : "+f"(c0), "+f"(c1), "+f"(c2), "+f"(c3)
        : "r"(a0), "r"(a1), "r"(a2), "r"(a3), "r"(b0), "r"(b1));
}
__device__ __forceinline__ void cp16(void* dst_smem, const void* src) {
    unsigned s = (unsigned)__cvta_generic_to_shared(dst_smem);
    asm volatile("cp.async.cg.shared.global [%0], [%1], 16;" :: "r"(s), "l"(src));
}
__device__ __forceinline__ void cp_commit() { asm volatile("cp.async.commit_group;"); }
__device__ __forceinline__ void cp_wait1()  { asm volatile("cp.async.wait_group 1;"); }
__device__ __forceinline__ void cp_wait0()  { asm volatile("cp.async.wait_group 0;"); }

// ---------------- float -> tf32-bits conversion (vectorized, optional scale) ----------------
__global__ __launch_bounds__(256) void cvt_kernel(
    const float* __restrict__ in, unsigned* __restrict__ out, int n, float scale)
{
    int i4 = (blockIdx.x * 256 + threadIdx.x) * 4;
    if (i4 >= n) return;
    float4 v = *(const float4*)(in + i4);
    uint4 u;
    u.x = f2tf(v.x * scale);
    u.y = f2tf(v.y * scale);
    u.z = f2tf(v.z * scale);
    u.w = f2tf(v.w * scale);
    *(uint4*)(out + i4) = u;
}

// ================= GEMM (tf32 bits in): C[M x 1536] = A @ W + bias =================
// Block tile (MT*32) x 128, ktile=32, 256 threads, warps 2(m) x 4(n), cp.async dbuf.
// MT=4 -> 128-row tile (main), MT=2 -> 64-row tile (ref).
#define G_APITCH 36
#define G_BPITCH 136

template<int MT>
__global__ __launch_bounds__(256) void gemm_tc(
    const unsigned* __restrict__ A, const unsigned* __restrict__ W,
    const float* __restrict__ bias, float* __restrict__ C)
{
    constexpr int TM = MT * 32;
    constexpr int OFF_A0 = 0;
    constexpr int OFF_A1 = TM * G_APITCH;
    constexpr int OFF_B0 = 2 * TM * G_APITCH;
    constexpr int OFF_B1 = OFF_B0 + 32 * G_BPITCH;

    extern __shared__ unsigned smu[];
    const int bm = blockIdx.y * TM;
    const int bn = blockIdx.x * 128;
    const int tid = threadIdx.x;
    const int lane = tid & 31, warp = tid >> 5;
    const int g = lane >> 2, l = lane & 3;
    const int wm = (warp >> 2) * (MT * 16);
    const int wn = (warp & 3) * 32;

    float c[MT][4][4];
#pragma unroll
    for (int mt = 0; mt < MT; mt++)
#pragma unroll
        for (int nt = 0; nt < 4; nt++)
#pragma unroll
            for (int i = 0; i < 4; i++) c[mt][nt][i] = 0.f;

    auto issue = [&](int kt, int buf) {
        unsigned* Ad = smu + (buf ? OFF_A1 : OFF_A0);
        unsigned* Bd = smu + (buf ? OFF_B1 : OFF_B0);
        const int k0 = kt * 32;
#pragma unroll
        for (int u = 0; u < MT; u++) {
            int i = tid + u * 256;              // TM*8 float4 for A
            int r = i >> 3, c4 = i & 7;
            cp16(Ad + r * G_APITCH + c4 * 4,
                 A + (size_t)(bm + r) * DIM + k0 + c4 * 4);
        }
#pragma unroll
        for (int u = 0; u < 4; u++) {
            int i = tid + u * 256;              // 1024 float4 for B
            int k = i >> 5, n4 = i & 31;
            cp16(Bd + k * G_BPITCH + n4 * 4,
                 W + (size_t)(k0 + k) * DIM + bn + n4 * 4);
        }
        cp_commit();
    };

    issue(0, 0);
    const int NKT = DIM / 32;  // 48
    for (int kt = 0; kt < NKT; kt++) {
        int buf = kt & 1;
        if (kt + 1 < NKT) { issue(kt + 1, buf ^ 1); cp_wait1(); }
        else              { cp_wait0(); }
        __syncthreads();

        const unsigned* As = smu + (buf ? OFF_A1 : OFF_A0);
        const unsigned* Bs = smu + (buf ? OFF_B1 : OFF_B0);

#pragma unroll
        for (int kk = 0; kk < 4; kk++) {
            unsigned a[MT][4];
#pragma unroll
            for (int mt = 0; mt < MT; mt++) {
                int row = wm + mt * 16;
                a[mt][0] = As[(row + g)     * G_APITCH + kk * 8 + l];
                a[mt][1] = As[(row + g + 8) * G_APITCH + kk * 8 + l];
                a[mt][2] = As[(row + g)     * G_APITCH + kk * 8 + l + 4];
                a[mt][3] = As[(row + g + 8) * G_APITCH + kk * 8 + l + 4];
            }
            unsigned b[4][2];
#pragma unroll
            for (int nt = 0; nt < 4; nt++) {
                int col = wn + nt * 8;
                b[nt][0] = Bs[(kk * 8 + l)     * G_BPITCH + col + g];
                b[nt][1] = Bs[(kk * 8 + l + 4) * G_BPITCH + col + g];
            }
#pragma unroll
            for (int mt = 0; mt < MT; mt++)
#pragma unroll
                for (int nt = 0; nt < 4; nt++)
                    mma_tf32(c[mt][nt][0], c[mt][nt][1], c[mt][nt][2], c[mt][nt][3],
                             a[mt][0], a[mt][1], a[mt][2], a[mt][3],
                             b[nt][0], b[nt][1]);
        }
        __syncthreads();
    }

#pragma unroll
    for (int mt = 0; mt < MT; mt++) {
#pragma unroll
        for (int nt = 0; nt < 4; nt++) {
            int row = bm + wm + mt * 16 + g;
            int col = bn + wn + nt * 8 + 2 * l;
            float b0 = bias[col], b1 = bias[col + 1];
            C[(size_t)row * DIM + col]           = c[mt][nt][0] + b0;
            C[(size_t)row * DIM + col + 1]       = c[mt][nt][1] + b1;
            C[(size_t)(row + 8) * DIM + col]     = c[mt][nt][2] + b0;
            C[(size_t)(row + 8) * DIM + col + 1] = c[mt][nt][3] + b1;
        }
    }
}

#define GEMM_SMEM_BYTES_M ((2 * 128 * G_APITCH + 2 * 32 * G_BPITCH) * 4)
#define GEMM_SMEM_BYTES_R ((2 * 64  * G_APITCH + 2 * 32 * G_BPITCH) * 4)

// ---------------- RMSNorm: float out (optional) + tf32-bits out (optional, scaled) ----------------
__global__ __launch_bounds__(256) void rmsnorm_kernel(
    const float* __restrict__ x, const float* __restrict__ g,
    float* __restrict__ out_f, unsigned* __restrict__ out_b, float bscale)
{
    const int row = blockIdx.x;
    const float* xr = x + (size_t)row * DIM;
    const int tid = threadIdx.x;

    float ss = 0.f;
    for (int i = tid; i < DIM; i += 256) {
        float v = xr[i];
        ss += v * v;
    }
#pragma unroll
    for (int off = 16; off; off >>= 1) ss += __shfl_xor_sync(0xffffffffu, ss, off);

    __shared__ float wsum[8];
    __shared__ float inv_s;
    if ((tid & 31) == 0) wsum[tid >> 5] = ss;
    __syncthreads();
    if (tid == 0) {
        float t = 0.f;
#pragma unroll
        for (int w = 0; w < 8; w++) t += wsum[w];
        inv_s = rsqrtf(t / (float)DIM + 1e-6f);
    }
    __syncthreads();
    float inv = inv_s;
    for (int i = tid; i < DIM; i += 256) {
        float v = xr[i] * inv * g[i];
        if (out_f) out_f[(size_t)row * DIM + i] = v;
        if (out_b) out_b[(size_t)row * DIM + i] = f2tf(v * bscale);
    }
}

// ---------------- RoPE -> tf32 bits (optional scale) ----------------
__global__ __launch_bounds__(256) void rope_kernel(
    const float* __restrict__ in, unsigned* __restrict__ out,
    const float* __restrict__ rc, const float* __restrict__ rs, float scale)
{
    int idx = blockIdx.x * 256 + threadIdx.x;
    if (idx >= T_LEN * (DIM / 2)) return;
    int t = idx / (DIM / 2);
    int p = idx % (DIM / 2);
    int h = p >> 6;
    int i = p & 63;
    size_t base = (size_t)t * DIM + h * DH + 2 * i;
    float e = in[base];
    float o = in[base + 1];
    float c = rc[t * (DH / 2) + i];
    float s = rs[t * (DH / 2) + i];
    out[base]     = f2tf((e * c - o * s) * scale);
    out[base + 1] = f2tf((e * s + o * c) * scale);
}

// ================= Flash attention (tf32 bits in) =================
// grid = (T_LEN/64, NH), 128 threads (4 warps). Warp w owns query rows [q0+16w, +16).
// KV tiles of 64 keys, double buffered via cp.async. Q pre-scaled by 1/sqrt(DH).
#define AT_QPITCH 132
#define AT_KPITCH 132
#define AT_VPITCH 136
#define AT_PPITCH 68
#define AT_OFF_Q  0
#define AT_OFF_K0 (64 * AT_QPITCH)
#define AT_OFF_K1 (AT_OFF_K0 + 64 * AT_KPITCH)
#define AT_OFF_V0 (AT_OFF_K1 + 64 * AT_KPITCH)
#define AT_OFF_V1 (AT_OFF_V0 + 64 * AT_VPITCH)
#define AT_OFF_P  (AT_OFF_V1 + 64 * AT_VPITCH)
#define ATTN_SMEM_BYTES ((AT_OFF_P + 4 * 16 * AT_PPITCH) * 4)

__global__ __launch_bounds__(128) void attn_tc(
    const unsigned* __restrict__ Q, const unsigned* __restrict__ Kp,
    const unsigned* __restrict__ Vp, float* __restrict__ Out,
    int Tk, int accumulate)
{
    extern __shared__ unsigned smu[];

    const int h = blockIdx.y;
    const int q0 = blockIdx.x * 64;
    const int tid = threadIdx.x;
    const int lane = tid & 31, warp = tid >> 5;
    const int g = lane >> 2, l = lane & 3;

    auto issue_tile = [&](int t, int buf) {
        unsigned* Kd = smu + (buf ? AT_OFF_K1 : AT_OFF_K0);
        unsigned* Vd = smu + (buf ? AT_OFF_V1 : AT_OFF_V0);
        const size_t rowbase = (size_t)(t * 64) * DIM + h * DH;
#pragma unroll
        for (int u = 0; u < 16; u++) {
            int i = tid + u * 128;              // 2048 x 16B for K
            int r = i >> 5, c4 = i & 31;
            cp16(Kd + r * AT_KPITCH + c4 * 4, Kp + rowbase + (size_t)r * DIM + c4 * 4);
        }
#pragma unroll
        for (int u = 0; u < 16; u++) {
            int i = tid + u * 128;              // 2048 x 16B for V
            int r = i >> 5, c4 = i & 31;
            cp16(Vd + r * AT_VPITCH + c4 * 4, Vp + rowbase + (size_t)r * DIM + c4 * 4);
        }
        cp_commit();
    };

    issue_tile(0, 0);

    // Q tile (already scaled tf32 bits)
#pragma unroll
    for (int u = 0; u < 16; u++) {
        int i = tid + u * 128;
        int r = i >> 5, c4 = i & 31;
        cp16(smu + AT_OFF_Q + r * AT_QPITCH + c4 * 4,
             Q + (size_t)(q0 + r) * DIM + h * DH + c4 * 4);
    }
    cp_commit();

    float o[16][4];
#pragma unroll
    for (int nt = 0; nt < 16; nt++)
#pragma unroll
        for (int i = 0; i < 4; i++) o[nt][i] = 0.f;
    float m0 = -1e30f, m1 = -1e30f, l0 = 0.f, l1 = 0.f;

    const int qrow = warp * 16;
    const int pbase = AT_OFF_P + warp * 16 * AT_PPITCH;
    const int ntiles = Tk / 64;

    for (int t = 0; t < ntiles; t++) {
        int buf = t & 1;
        if (t + 1 < ntiles) { issue_tile(t + 1, buf ^ 1); cp_wait1(); }
        else                { cp_wait0(); }
        __syncthreads();

        const unsigned* Ks = smu + (buf ? AT_OFF_K1 : AT_OFF_K0);
        const unsigned* Vs = smu + (buf ? AT_OFF_V1 : AT_OFF_V0);

        // ---- S = Q K^T ----
        float s[8][4];
#pragma unroll
        for (int nt = 0; nt < 8; nt++)
#pragma unroll
            for (int i = 0; i < 4; i++) s[nt][i] = 0.f;

#pragma unroll
        for (int kk = 0; kk < 16; kk++) {
            unsigned a0 = smu[AT_OFF_Q + (qrow + g)     * AT_QPITCH + kk * 8 + l];
            unsigned a1 = smu[AT_OFF_Q + (qrow + g + 8) * AT_QPITCH + kk * 8 + l];
            unsigned a2 = smu[AT_OFF_Q + (qrow + g)     * AT_QPITCH + kk * 8 + l + 4];
            unsigned a3 = smu[AT_OFF_Q + (qrow + g + 8) * AT_QPITCH + kk * 8 + l + 4];
#pragma unroll
            for (int nt = 0; nt < 8; nt++) {
                unsigned b0 = Ks[(nt * 8 + g) * AT_KPITCH + kk * 8 + l];
                unsigned b1 = Ks[(nt * 8 + g) * AT_KPITCH + kk * 8 + l + 4];
                mma_tf32(s[nt][0], s[nt][1], s[nt][2], s[nt][3], a0, a1, a2, a3, b0, b1);
            }
        }

        // ---- online softmax (rows warp-local; quad = 4 lanes of one row) ----
        float tm0 = -1e30f, tm1 = -1e30f;
#pragma unroll
        for (int nt = 0; nt < 8; nt++) {
            tm0 = fmaxf(tm0, fmaxf(s[nt][0], s[nt][1]));
            tm1 = fmaxf(tm1, fmaxf(s[nt][2], s[nt][3]));
        }
        tm0 = fmaxf(tm0, __shfl_xor_sync(0xffffffffu, tm0, 1));
        tm0 = fmaxf(tm0, __shfl_xor_sync(0xffffffffu, tm0, 2));
        tm1 = fmaxf(tm1, __shfl_xor_sync(0xffffffffu, tm1, 1));
        tm1 = fmaxf(tm1, __shfl_xor_sync(0xffffffffu, tm1, 2));
        float mn0 = fmaxf(m0, tm0), mn1 = fmaxf(m1, tm1);
        float al0 = __expf(m0 - mn0), al1 = __expf(m1 - mn1);
        m0 = mn0; m1 = mn1;

        float sum0 = 0.f, sum1 = 0.f;
#pragma unroll
        for (int nt = 0; nt < 8; nt++) {
            float p0 = __expf(s[nt][0] - mn0);
            float p1 = __expf(s[nt][1] - mn0);
            float p2 = __expf(s[nt][2] - mn1);
            float p3 = __expf(s[nt][3] - mn1);
            sum0 += p0 + p1;
            sum1 += p2 + p3;
            unsigned* d0 = smu + pbase + g * AT_PPITCH + nt * 8 + 2 * l;
            unsigned* d1 = smu + pbase + (g + 8) * AT_PPITCH + nt * 8 + 2 * l;
            d0[0] = f2tf(p0); d0[1] = f2tf(p1);
            d1[0] = f2tf(p2); d1[1] = f2tf(p3);
        }
        sum0 += __shfl_xor_sync(0xffffffffu, sum0, 1);
        sum0 += __shfl_xor_sync(0xffffffffu, sum0, 2);
        sum1 += __shfl_xor_sync(0xffffffffu, sum1, 1);
        sum1 += __shfl_xor_sync(0xffffffffu, sum1, 2);
        l0 = l0 * al0 + sum0;
        l1 = l1 * al1 + sum1;
#pragma unroll
        for (int nt = 0; nt < 16; nt++) {
            o[nt][0] *= al0; o[nt][1] *= al0;
            o[nt][2] *= al1; o[nt][3] *= al1;
        }
        __syncwarp();

        // ---- O += P @ V ----
#pragma unroll
        for (int kt = 0; kt < 8; kt++) {
            unsigned a0 = smu[pbase + g * AT_PPITCH + kt * 8 + l];
            unsigned a1 = smu[pbase + (g + 8) * AT_PPITCH + kt * 8 + l];
            unsigned a2 = smu[pbase + g * AT_PPITCH + kt * 8 + l + 4];
            unsigned a3 = smu[pbase + (g + 8) * AT_PPITCH + kt * 8 + l + 4];
#pragma unroll
            for (int nt = 0; nt < 16; nt++) {
                unsigned b0 = Vs[(kt * 8 + l)     * AT_VPITCH + nt * 8 + g];
                unsigned b1 = Vs[(kt * 8 + l + 4) * AT_VPITCH + nt * 8 + g];
                mma_tf32(o[nt][0], o[nt][1], o[nt][2], o[nt][3], a0, a1, a2, a3, b0, b1);
            }
        }
        __syncthreads();
    }

    // ---- epilogue ----
    float inv0 = 1.f / l0, inv1 = 1.f / l1;
    int row0 = q0 + warp * 16 + g;
    int row1 = row0 + 8;
    if (accumulate) {
#pragma unroll
        for (int nt = 0; nt < 16; nt++) {
            int col = h * DH + nt * 8 + 2 * l;
            size_t i0 = (size_t)row0 * DIM + col;
            size_t i1 = (size_t)row1 * DIM + col;
            Out[i0]     += o[nt][0] * inv0;
            Out[i0 + 1] += o[nt][1] * inv0;
            Out[i1]     += o[nt][2] * inv1;
            Out[i1 + 1] += o[nt][3] * inv1;
        }
    } else {
#pragma unroll
        for (int nt = 0; nt < 16; nt++) {
            int col = h * DH + nt * 8 + 2 * l;
            size_t i0 = (size_t)row0 * DIM + col;
            size_t i1 = (size_t)row1 * DIM + col;
            Out[i0]     = o[nt][0] * inv0;
            Out[i0 + 1] = o[nt][1] * inv0;
            Out[i1]     = o[nt][2] * inv1;
            Out[i1 + 1] = o[nt][3] * inv1;
        }
    }
}

// ---------------- launch ----------------
extern "C" void kernel_launch(void* const* d_in, const int* in_sizes, int n_in,
                              void* d_out, int out_size)
{
    const float* hs   = (const float*)d_in[0];
    const float* rhs  = (const float*)d_in[1];
    const float* rcos = (const float*)d_in[2];
    const float* rsin = (const float*)d_in[3];
    const float* Wq   = (const float*)d_in[4];
    const float* bq   = (const float*)d_in[5];
    const float* Wk   = (const float*)d_in[6];
    const float* bk   = (const float*)d_in[7];
    const float* Wv   = (const float*)d_in[8];
    const float* bv   = (const float*)d_in[9];
    const float* Wkr  = (const float*)d_in[10];
    const float* bkr  = (const float*)d_in[11];
    const float* Wvr  = (const float*)d_in[12];
    const float* bvr  = (const float*)d_in[13];
    const float* Wo   = (const float*)d_in[14];
    const float* bo   = (const float*)d_in[15];
    const float* gq   = (const float*)d_in[16];
    const float* gk   = (const float*)d_in[17];
    float* out = (float*)d_out;

    float *qlin, *klin, *vlin, *krlin, *vrlin, *attn;
    unsigned *hsb, *rhsb, *wb, *qtfb, *qropeb, *kb, *vb, *krb, *vrb, *attnb;
    cudaGetSymbolAddress((void**)&qlin,  g_qlin);
    cudaGetSymbolAddress((void**)&klin,  g_klin);
    cudaGetSymbolAddress((void**)&vlin,  g_vlin);
    cudaGetSymbolAddress((void**)&krlin, g_krlin);
    cudaGetSymbolAddress((void**)&vrlin, g_vrlin);
    cudaGetSymbolAddress((void**)&attn,  g_attn);
    cudaGetSymbolAddress((void**)&hsb,   g_hsb);
    cudaGetSymbolAddress((void**)&rhsb,  g_rhsb);
    cudaGetSymbolAddress((void**)&wb,    g_wb);
    cudaGetSymbolAddress((void**)&qtfb,  g_qtfb);
    cudaGetSymbolAddress((void**)&qropeb,g_qropeb);
    cudaGetSymbolAddress((void**)&kb,    g_kb);
    cudaGetSymbolAddress((void**)&vb,    g_vb);
    cudaGetSymbolAddress((void**)&krb,   g_krb);
    cudaGetSymbolAddress((void**)&vrb,   g_vrb);
    cudaGetSymbolAddress((void**)&attnb, g_attnb);

    cudaFuncSetAttribute(gemm_tc<4>,
                         cudaFuncAttributeMaxDynamicSharedMemorySize, GEMM_SMEM_BYTES_M);
    cudaFuncSetAttribute(gemm_tc<2>,
                         cudaFuncAttributeMaxDynamicSharedMemorySize, GEMM_SMEM_BYTES_R);
    cudaFuncSetAttribute(attn_tc,
                         cudaFuncAttributeMaxDynamicSharedMemorySize, ATTN_SMEM_BYTES);

    const float scale = 0.08838834764831845f;  // 1/sqrt(128)
    const int NW = DIM * DIM;                   // weight elements
    const int NT = T_LEN * DIM, NR = TR_LEN * DIM;
    const int CB = 256 * 4;                     // elems per cvt block

    // ---- convert inputs to tf32 bits ----
    cvt_kernel<<<(NT + CB - 1) / CB, 256>>>(hs,  hsb,  NT, 1.f);
    cvt_kernel<<<(NR + CB - 1) / CB, 256>>>(rhs, rhsb, NR, 1.f);
    cvt_kernel<<<(NW + CB - 1) / CB, 256>>>(Wq,  wb + 0 * (size_t)NW, NW, 1.f);
    cvt_kernel<<<(NW + CB - 1) / CB, 256>>>(Wk,  wb + 1 * (size_t)NW, NW, 1.f);
    cvt_kernel<<<(NW + CB - 1) / CB, 256>>>(Wv,  wb + 2 * (size_t)NW, NW, 1.f);
    cvt_kernel<<<(NW + CB - 1) / CB, 256>>>(Wkr, wb + 3 * (size_t)NW, NW, 1.f);
    cvt_kernel<<<(NW + CB - 1) / CB, 256>>>(Wvr, wb + 4 * (size_t)NW, NW, 1.f);
    cvt_kernel<<<(NW + CB - 1) / CB, 256>>>(Wo,  wb + 5 * (size_t)NW, NW, 1.f);

    // ---- projections ----
    dim3 grid_main(DIM / 128, T_LEN / 128);   // (12, 32)
    dim3 grid_ref(DIM / 128, TR_LEN / 64);    // (12, 16)
    gemm_tc<4><<<grid_main, 256, GEMM_SMEM_BYTES_M>>>(hsb,  wb + 0 * (size_t)NW, bq,  qlin);
    gemm_tc<4><<<grid_main, 256, GEMM_SMEM_BYTES_M>>>(hsb,  wb + 1 * (size_t)NW, bk,  klin);
    gemm_tc<4><<<grid_main, 256, GEMM_SMEM_BYTES_M>>>(hsb,  wb + 2 * (size_t)NW, bv,  vlin);
    gemm_tc<2><<<grid_ref,  256, GEMM_SMEM_BYTES_R>>>(rhsb, wb + 3 * (size_t)NW, bkr, krlin);
    gemm_tc<2><<<grid_ref,  256, GEMM_SMEM_BYTES_R>>>(rhsb, wb + 4 * (size_t)NW, bvr, vrlin);

    // ---- V -> bits ----
    cvt_kernel<<<(NT + CB - 1) / CB, 256>>>(vlin,  vb,  NT, 1.f);
    cvt_kernel<<<(NR + CB - 1) / CB, 256>>>(vrlin, vrb, NR, 1.f);

    // ---- RMSNorms ----
    rmsnorm_kernel<<<T_LEN, 256>>>(qlin,  gq, qlin, qtfb, scale);  // float for rope + scaled bits for ref attn
    rmsnorm_kernel<<<T_LEN, 256>>>(klin,  gk, klin, nullptr, 1.f);
    rmsnorm_kernel<<<TR_LEN, 256>>>(krlin, gk, nullptr, krb, 1.f);

    // ---- RoPE -> bits ----
    int rope_blocks = (T_LEN * (DIM / 2) + 255) / 256;
    rope_kernel<<<rope_blocks, 256>>>(qlin, qropeb, rcos, rsin, scale);
    rope_kernel<<<rope_blocks, 256>>>(klin, kb,     rcos, rsin, 1.f);

    // ---- attention: ref writes, main accumulates ----
    dim3 attn_grid(T_LEN / 64, NH);  // (64, 12)
    attn_tc<<<attn_grid, 128, ATTN_SMEM_BYTES>>>(qtfb,   krb, vrb, attn, TR_LEN, 0);
    attn_tc<<<attn_grid, 128, ATTN_SMEM_BYTES>>>(qropeb, kb,  vb,  attn, T_LEN, 1);

    // ---- output projection ----
    cvt_kernel<<<(NT + CB - 1) / CB, 256>>>(attn, attnb, NT, 1.f);
    gemm_tc<4><<<grid_main, 256, GEMM_SMEM_BYTES_M>>>(attnb, wb + 5 * (size_t)NW, bo, out);
}

// round 5
// speedup vs baseline: 8.6373x; 1.7206x over previous
#include <cuda_runtime.h>
#include <cuda_fp16.h>
#include <math.h>

#define T_LEN 4096
#define TR_LEN 1024
#define DIM 1536
#define NH 12
#define DH 128

// ---------------- scratch (device globals; no allocation allowed) ----------------
__device__ float g_qlin[T_LEN * DIM];
__device__ float g_klin[T_LEN * DIM];
__device__ float g_vlin[T_LEN * DIM];
__device__ float g_krlin[TR_LEN * DIM];
__device__ float g_vrlin[TR_LEN * DIM];
__device__ float g_attn[T_LEN * DIM];

// fp16 buffers
__device__ __half g_hsh[T_LEN * DIM];
__device__ __half g_rhsh[TR_LEN * DIM];
__device__ __half g_wth[6 * DIM * DIM];   // Wq,Wk,Wv,Wkr,Wvr,Wo transposed [n][k]
__device__ __half g_qh[T_LEN * DIM];      // rms(q)*scale
__device__ __half g_qroph[T_LEN * DIM];   // rope(rms(q))*scale
__device__ __half g_kh[T_LEN * DIM];      // rope(rms(k))
__device__ __half g_vth[DIM * T_LEN];     // V transposed [h*DH + d][t]
__device__ __half g_krh[TR_LEN * DIM];    // rms(ref k)
__device__ __half g_vrth[DIM * TR_LEN];   // ref V transposed
__device__ __half g_attnh[T_LEN * DIM];

// ---------------- PTX helpers ----------------
__device__ __forceinline__ void mma_f16(float& c0, float& c1, float& c2, float& c3,
                                        unsigned a0, unsigned a1, unsigned a2, unsigned a3,
                                        unsigned b0, unsigned b1) {
    asm volatile(
        "mma.sync.aligned.m16n8k16.row.col.f32.f16.f16.f32 "
        "{%0,%1,%2,%3},{%4,%5,%6,%7},{%8,%9},{%0,%1,%2,%3};"
        : "+f"(c0), "+f"(c1), "+f"(c2), "+f"(c3)
        : "r"(a0), "r"(a1), "r"(a2), "r"(a3), "r"(b0), "r"(b1));
}
__device__ __forceinline__ void cp16(void* dst_smem, const void* src) {
    unsigned s = (unsigned)__cvta_generic_to_shared(dst_smem);
    asm volatile("cp.async.cg.shared.global [%0], [%1], 16;" :: "r"(s), "l"(src));
}
__device__ __forceinline__ void cp_commit() { asm volatile("cp.async.commit_group;"); }
__device__ __forceinline__ void cp_wait1()  { asm volatile("cp.async.wait_group 1;"); }
__device__ __forceinline__ void cp_wait0()  { asm volatile("cp.async.wait_group 0;"); }
__device__ __forceinline__ unsigned h2u(__half2 h) { return *(unsigned*)&h; }

// ---------------- float -> half conversion (vectorized, optional scale) ----------------
__global__ __launch_bounds__(256) void cvt_h(
    const float* __restrict__ in, __half* __restrict__ out, int n, float scale)
{
    int i4 = (blockIdx.x * 256 + threadIdx.x) * 4;
    if (i4 >= n) return;
    float4 v = *(const float4*)(in + i4);
    __half2 h0 = __float22half2_rn(make_float2(v.x * scale, v.y * scale));
    __half2 h1 = __float22half2_rn(make_float2(v.z * scale, v.w * scale));
    uint2 u; u.x = h2u(h0); u.y = h2u(h1);
    *(uint2*)(out + i4) = u;
}

// ---------------- tiled transpose: in float [R][C] -> out half [C][R] ----------------
__global__ __launch_bounds__(256) void transpose_h(
    const float* __restrict__ in, __half* __restrict__ out, int R, int C)
{
    __shared__ float t[32][33];
    int c0 = blockIdx.x * 32, r0 = blockIdx.y * 32;
    int tx = threadIdx.x, ty = threadIdx.y;   // block (32,8)
#pragma unroll
    for (int yy = 0; yy < 32; yy += 8)
        t[ty + yy][tx] = in[(size_t)(r0 + ty + yy) * C + c0 + tx];
    __syncthreads();
#pragma unroll
    for (int yy = 0; yy < 32; yy += 8)
        out[(size_t)(c0 + ty + yy) * R + r0 + tx] = __float2half_rn(t[tx][ty + yy]);
}

// ================= GEMM (fp16 mma): C[M x 1536] = A @ W + bias =================
// A: half [m][k] row-major. Wt: half [n][k] (pre-transposed). ktile=32, 256 threads.
// Block tile (MT*32) x 128, warps 2(m) x 4(n). Smem pitch 40 halves = 20 unsigned.
#define GP 20   // pitch in unsigned (40 halves)

template<int MT>
__global__ __launch_bounds__(256) void gemm_f16(
    const __half* __restrict__ A, const __half* __restrict__ Wt,
    const float* __restrict__ bias, float* __restrict__ C)
{
    constexpr int TM = MT * 32;
    constexpr int OFF_A0 = 0;
    constexpr int OFF_A1 = TM * GP;
    constexpr int OFF_B0 = 2 * TM * GP;
    constexpr int OFF_B1 = OFF_B0 + 128 * GP;

    extern __shared__ unsigned smu[];
    const int bm = blockIdx.y * TM;
    const int bn = blockIdx.x * 128;
    const int tid = threadIdx.x;
    const int lane = tid & 31, warp = tid >> 5;
    const int g = lane >> 2, l = lane & 3;
    const int wm = (warp >> 2) * (MT * 16);
    const int wn = (warp & 3) * 32;

    float c[MT][4][4];
#pragma unroll
    for (int mt = 0; mt < MT; mt++)
#pragma unroll
        for (int nt = 0; nt < 4; nt++)
#pragma unroll
            for (int i = 0; i < 4; i++) c[mt][nt][i] = 0.f;

    auto issue = [&](int kt, int buf) {
        unsigned* Au = smu + (buf ? OFF_A1 : OFF_A0);
        unsigned* Bu = smu + (buf ? OFF_B1 : OFF_B0);
        const int k0 = kt * 32;
#pragma unroll
        for (int u = 0; u < MT / 2; u++) {
            int i = tid + u * 256;              // TM*4 cp16 for A (row = 64B)
            int r = i >> 2, c4 = i & 3;
            cp16(Au + r * GP + c4 * 4, A + (size_t)(bm + r) * DIM + k0 + c4 * 8);
        }
#pragma unroll
        for (int u = 0; u < 2; u++) {
            int i = tid + u * 256;              // 512 cp16 for B
            int r = i >> 2, c4 = i & 3;
            cp16(Bu + r * GP + c4 * 4, Wt + (size_t)(bn + r) * DIM + k0 + c4 * 8);
        }
        cp_commit();
    };

    issue(0, 0);
    const int NKT = DIM / 32;  // 48
    for (int kt = 0; kt < NKT; kt++) {
        int buf = kt & 1;
        if (kt + 1 < NKT) { issue(kt + 1, buf ^ 1); cp_wait1(); }
        else              { cp_wait0(); }
        __syncthreads();

        const unsigned* As = smu + (buf ? OFF_A1 : OFF_A0);
        const unsigned* Bs = smu + (buf ? OFF_B1 : OFF_B0);

#pragma unroll
        for (int kk = 0; kk < 2; kk++) {
            unsigned a[MT][4];
#pragma unroll
            for (int mt = 0; mt < MT; mt++) {
                int row = wm + mt * 16;
                a[mt][0] = As[(row + g)     * GP + kk * 8 + l];
                a[mt][1] = As[(row + g + 8) * GP + kk * 8 + l];
                a[mt][2] = As[(row + g)     * GP + kk * 8 + l + 4];
                a[mt][3] = As[(row + g + 8) * GP + kk * 8 + l + 4];
            }
            unsigned b[4][2];
#pragma unroll
            for (int nt = 0; nt < 4; nt++) {
                int col = wn + nt * 8;
                b[nt][0] = Bs[(col + g) * GP + kk * 8 + l];
                b[nt][1] = Bs[(col + g) * GP + kk * 8 + l + 4];
            }
#pragma unroll
            for (int mt = 0; mt < MT; mt++)
#pragma unroll
                for (int nt = 0; nt < 4; nt++)
                    mma_f16(c[mt][nt][0], c[mt][nt][1], c[mt][nt][2], c[mt][nt][3],
                            a[mt][0], a[mt][1], a[mt][2], a[mt][3],
                            b[nt][0], b[nt][1]);
        }
        __syncthreads();
    }

#pragma unroll
    for (int mt = 0; mt < MT; mt++) {
#pragma unroll
        for (int nt = 0; nt < 4; nt++) {
            int row = bm + wm + mt * 16 + g;
            int col = bn + wn + nt * 8 + 2 * l;
            float b0 = bias[col], b1 = bias[col + 1];
            C[(size_t)row * DIM + col]           = c[mt][nt][0] + b0;
            C[(size_t)row * DIM + col + 1]       = c[mt][nt][1] + b1;
            C[(size_t)(row + 8) * DIM + col]     = c[mt][nt][2] + b0;
            C[(size_t)(row + 8) * DIM + col + 1] = c[mt][nt][3] + b1;
        }
    }
}

#define GEMM_SMEM_M ((4 * 128 * GP) * 4)            // MT=4: 40960 B
#define GEMM_SMEM_R ((2 * 64 * GP + 2 * 128 * GP) * 4)  // MT=2: 30720 B

// ---------------- RMSNorm: optional float out, optional half out (scaled) ----------------
__global__ __launch_bounds__(256) void rmsnorm_kernel(
    const float* __restrict__ x, const float* __restrict__ g,
    float* __restrict__ out_f, __half* __restrict__ out_b, float bscale)
{
    const int row = blockIdx.x;
    const float* xr = x + (size_t)row * DIM;
    const int tid = threadIdx.x;

    float ss = 0.f;
    for (int i = tid; i < DIM; i += 256) {
        float v = xr[i];
        ss += v * v;
    }
#pragma unroll
    for (int off = 16; off; off >>= 1) ss += __shfl_xor_sync(0xffffffffu, ss, off);

    __shared__ float wsum[8];
    __shared__ float inv_s;
    if ((tid & 31) == 0) wsum[tid >> 5] = ss;
    __syncthreads();
    if (tid == 0) {
        float t = 0.f;
#pragma unroll
        for (int w = 0; w < 8; w++) t += wsum[w];
        inv_s = rsqrtf(t / (float)DIM + 1e-6f);
    }
    __syncthreads();
    float inv = inv_s;
    for (int i = tid; i < DIM; i += 256) {
        float v = xr[i] * inv * g[i];
        if (out_f) out_f[(size_t)row * DIM + i] = v;
        if (out_b) out_b[(size_t)row * DIM + i] = __float2half_rn(v * bscale);
    }
}

// ---------------- RoPE -> half (optional scale) ----------------
__global__ __launch_bounds__(256) void rope_kernel(
    const float* __restrict__ in, __half* __restrict__ out,
    const float* __restrict__ rc, const float* __restrict__ rs, float scale)
{
    int idx = blockIdx.x * 256 + threadIdx.x;
    if (idx >= T_LEN * (DIM / 2)) return;
    int t = idx / (DIM / 2);
    int p = idx % (DIM / 2);
    int h = p >> 6;
    int i = p & 63;
    size_t base = (size_t)t * DIM + h * DH + 2 * i;
    float e = in[base];
    float o = in[base + 1];
    float c = rc[t * (DH / 2) + i];
    float s = rs[t * (DH / 2) + i];
    *(__half2*)(out + base) =
        __float22half2_rn(make_float2((e * c - o * s) * scale, (e * s + o * c) * scale));
}

// ================= Flash attention (fp16 mma) =================
// grid (T_LEN/64, NH), 128 threads (4 warps); warp w owns q rows [q0+16w, +16).
// Q,K: half [t][DIM] (head slice), V: half [h*DH+d][Tk] transposed. Q pre-scaled.
// Smem pitches: Q,K 136 halves (68 u); V,P 72 halves (36 u).
#define AQ 68
#define AV 36
#define AT_OFF_Q  0
#define AT_OFF_K0 (64 * AQ)
#define AT_OFF_K1 (AT_OFF_K0 + 64 * AQ)
#define AT_OFF_V0 (AT_OFF_K1 + 64 * AQ)
#define AT_OFF_V1 (AT_OFF_V0 + 128 * AV)
#define AT_OFF_P  (AT_OFF_V1 + 128 * AV)
#define ATTN_SMEM_BYTES ((AT_OFF_P + 4 * 16 * AV) * 4)   // 98304 B

__global__ __launch_bounds__(128) void attn_f16(
    const __half* __restrict__ Q, const __half* __restrict__ Kp,
    const __half* __restrict__ Vt, float* __restrict__ Out,
    int Tk, int accumulate)
{
    extern __shared__ unsigned smu[];

    const int h = blockIdx.y;
    const int q0 = blockIdx.x * 64;
    const int tid = threadIdx.x;
    const int lane = tid & 31, warp = tid >> 5;
    const int g = lane >> 2, l = lane & 3;

    auto issue_tile = [&](int t, int buf) {
        unsigned* Ku = smu + (buf ? AT_OFF_K1 : AT_OFF_K0);
        unsigned* Vu = smu + (buf ? AT_OFF_V1 : AT_OFF_V0);
        const size_t krow = (size_t)(t * 64) * DIM + h * DH;
#pragma unroll
        for (int u = 0; u < 8; u++) {
            int i = tid + u * 128;              // K: 64 rows x 16 cp16
            int r = i >> 4, c4 = i & 15;
            cp16(Ku + r * AQ + c4 * 4, Kp + krow + (size_t)r * DIM + c4 * 8);
        }
#pragma unroll
        for (int u = 0; u < 8; u++) {
            int i = tid + u * 128;              // V: 128 rows x 8 cp16
            int r = i >> 3, c4 = i & 7;
            cp16(Vu + r * AV + c4 * 4,
                 Vt + (size_t)(h * DH + r) * Tk + t * 64 + c4 * 8);
        }
        cp_commit();
    };

    issue_tile(0, 0);

    // Q tile (pre-scaled half)
#pragma unroll
    for (int u = 0; u < 8; u++) {
        int i = tid + u * 128;
        int r = i >> 4, c4 = i & 15;
        cp16(smu + AT_OFF_Q + r * AQ + c4 * 4,
             Q + (size_t)(q0 + r) * DIM + h * DH + c4 * 8);
    }
    cp_commit();

    float o[16][4];
#pragma unroll
    for (int nt = 0; nt < 16; nt++)
#pragma unroll
        for (int i = 0; i < 4; i++) o[nt][i] = 0.f;
    float m0 = -1e30f, m1 = -1e30f, l0 = 0.f, l1 = 0.f;

    const int qrow = warp * 16;
    const int pbase = AT_OFF_P + warp * 16 * AV;
    const int ntiles = Tk / 64;

    for (int t = 0; t < ntiles; t++) {
        int buf = t & 1;
        if (t + 1 < ntiles) { issue_tile(t + 1, buf ^ 1); cp_wait1(); }
        else                { cp_wait0(); }
        __syncthreads();

        const unsigned* Ks = smu + (buf ? AT_OFF_K1 : AT_OFF_K0);
        const unsigned* Vs = smu + (buf ? AT_OFF_V1 : AT_OFF_V0);

        // ---- S = Q K^T (k = dh, 8 chunks of 16) ----
        float s[8][4];
#pragma unroll
        for (int nt = 0; nt < 8; nt++)
#pragma unroll
            for (int i = 0; i < 4; i++) s[nt][i] = 0.f;

#pragma unroll
        for (int kk = 0; kk < 8; kk++) {
            unsigned a0 = smu[AT_OFF_Q + (qrow + g)     * AQ + kk * 8 + l];
            unsigned a1 = smu[AT_OFF_Q + (qrow + g + 8) * AQ + kk * 8 + l];
            unsigned a2 = smu[AT_OFF_Q + (qrow + g)     * AQ + kk * 8 + l + 4];
            unsigned a3 = smu[AT_OFF_Q + (qrow + g + 8) * AQ + kk * 8 + l + 4];
#pragma unroll
            for (int nt = 0; nt < 8; nt++) {
                unsigned b0 = Ks[(nt * 8 + g) * AQ + kk * 8 + l];
                unsigned b1 = Ks[(nt * 8 + g) * AQ + kk * 8 + l + 4];
                mma_f16(s[nt][0], s[nt][1], s[nt][2], s[nt][3], a0, a1, a2, a3, b0, b1);
            }
        }

        // ---- online softmax (rows warp-local; quad = 4 lanes of one row) ----
        float tm0 = -1e30f, tm1 = -1e30f;
#pragma unroll
        for (int nt = 0; nt < 8; nt++) {
            tm0 = fmaxf(tm0, fmaxf(s[nt][0], s[nt][1]));
            tm1 = fmaxf(tm1, fmaxf(s[nt][2], s[nt][3]));
        }
        tm0 = fmaxf(tm0, __shfl_xor_sync(0xffffffffu, tm0, 1));
        tm0 = fmaxf(tm0, __shfl_xor_sync(0xffffffffu, tm0, 2));
        tm1 = fmaxf(tm1, __shfl_xor_sync(0xffffffffu, tm1, 1));
        tm1 = fmaxf(tm1, __shfl_xor_sync(0xffffffffu, tm1, 2));
        float mn0 = fmaxf(m0, tm0), mn1 = fmaxf(m1, tm1);
        float al0 = __expf(m0 - mn0), al1 = __expf(m1 - mn1);
        m0 = mn0; m1 = mn1;

        float sum0 = 0.f, sum1 = 0.f;
#pragma unroll
        for (int nt = 0; nt < 8; nt++) {
            float p0 = __expf(s[nt][0] - mn0);
            float p1 = __expf(s[nt][1] - mn0);
            float p2 = __expf(s[nt][2] - mn1);
            float p3 = __expf(s[nt][3] - mn1);
            sum0 += p0 + p1;
            sum1 += p2 + p3;
            smu[pbase + g       * AV + nt * 4 + l] = h2u(__float22half2_rn(make_float2(p0, p1)));
            smu[pbase + (g + 8) * AV + nt * 4 + l] = h2u(__float22half2_rn(make_float2(p2, p3)));
        }
        sum0 += __shfl_xor_sync(0xffffffffu, sum0, 1);
        sum0 += __shfl_xor_sync(0xffffffffu, sum0, 2);
        sum1 += __shfl_xor_sync(0xffffffffu, sum1, 1);
        sum1 += __shfl_xor_sync(0xffffffffu, sum1, 2);
        l0 = l0 * al0 + sum0;
        l1 = l1 * al1 + sum1;
#pragma unroll
        for (int nt = 0; nt < 16; nt++) {
            o[nt][0] *= al0; o[nt][1] *= al0;
            o[nt][2] *= al1; o[nt][3] *= al1;
        }
        __syncwarp();

        // ---- O += P @ V (k = keys, 4 chunks of 16; n = dh, 16 blocks of 8) ----
#pragma unroll
        for (int kt = 0; kt < 4; kt++) {
            unsigned a0 = smu[pbase + g       * AV + kt * 8 + l];
            unsigned a1 = smu[pbase + (g + 8) * AV + kt * 8 + l];
            unsigned a2 = smu[pbase + g       * AV + kt * 8 + l + 4];
            unsigned a3 = smu[pbase + (g + 8) * AV + kt * 8 + l + 4];
#pragma unroll
            for (int nt = 0; nt < 16; nt++) {
                unsigned b0 = Vs[(nt * 8 + g) * AV + kt * 8 + l];
                unsigned b1 = Vs[(nt * 8 + g) * AV + kt * 8 + l + 4];
                mma_f16(o[nt][0], o[nt][1], o[nt][2], o[nt][3], a0, a1, a2, a3, b0, b1);
            }
        }
        __syncthreads();
    }

    // ---- epilogue ----
    float inv0 = 1.f / l0, inv1 = 1.f / l1;
    int row0 = q0 + warp * 16 + g;
    int row1 = row0 + 8;
    if (accumulate) {
#pragma unroll
        for (int nt = 0; nt < 16; nt++) {
            int col = h * DH + nt * 8 + 2 * l;
            size_t i0 = (size_t)row0 * DIM + col;
            size_t i1 = (size_t)row1 * DIM + col;
            Out[i0]     += o[nt][0] * inv0;
            Out[i0 + 1] += o[nt][1] * inv0;
            Out[i1]     += o[nt][2] * inv1;
            Out[i1 + 1] += o[nt][3] * inv1;
        }
    } else {
#pragma unroll
        for (int nt = 0; nt < 16; nt++) {
            int col = h * DH + nt * 8 + 2 * l;
            size_t i0 = (size_t)row0 * DIM + col;
            size_t i1 = (size_t)row1 * DIM + col;
            Out[i0]     = o[nt][0] * inv0;
            Out[i0 + 1] = o[nt][1] * inv0;
            Out[i1]     = o[nt][2] * inv1;
            Out[i1 + 1] = o[nt][3] * inv1;
        }
    }
}

// ---------------- launch ----------------
extern "C" void kernel_launch(void* const* d_in, const int* in_sizes, int n_in,
                              void* d_out, int out_size)
{
    const float* hs   = (const float*)d_in[0];
    const float* rhs  = (const float*)d_in[1];
    const float* rcos = (const float*)d_in[2];
    const float* rsin = (const float*)d_in[3];
    const float* Wq   = (const float*)d_in[4];
    const float* bq   = (const float*)d_in[5];
    const float* Wk   = (const float*)d_in[6];
    const float* bk   = (const float*)d_in[7];
    const float* Wv   = (const float*)d_in[8];
    const float* bv   = (const float*)d_in[9];
    const float* Wkr  = (const float*)d_in[10];
    const float* bkr  = (const float*)d_in[11];
    const float* Wvr  = (const float*)d_in[12];
    const float* bvr  = (const float*)d_in[13];
    const float* Wo   = (const float*)d_in[14];
    const float* bo   = (const float*)d_in[15];
    const float* gq   = (const float*)d_in[16];
    const float* gk   = (const float*)d_in[17];
    float* out = (float*)d_out;

    float *qlin, *klin, *vlin, *krlin, *vrlin, *attn;
    __half *hsh, *rhsh, *wth, *qh, *qroph, *kh, *vth, *krh, *vrth, *attnh;
    cudaGetSymbolAddress((void**)&qlin,  g_qlin);
    cudaGetSymbolAddress((void**)&klin,  g_klin);
    cudaGetSymbolAddress((void**)&vlin,  g_vlin);
    cudaGetSymbolAddress((void**)&krlin, g_krlin);
    cudaGetSymbolAddress((void**)&vrlin, g_vrlin);
    cudaGetSymbolAddress((void**)&attn,  g_attn);
    cudaGetSymbolAddress((void**)&hsh,   g_hsh);
    cudaGetSymbolAddress((void**)&rhsh,  g_rhsh);
    cudaGetSymbolAddress((void**)&wth,   g_wth);
    cudaGetSymbolAddress((void**)&qh,    g_qh);
    cudaGetSymbolAddress((void**)&qroph, g_qroph);
    cudaGetSymbolAddress((void**)&kh,    g_kh);
    cudaGetSymbolAddress((void**)&vth,   g_vth);
    cudaGetSymbolAddress((void**)&krh,   g_krh);
    cudaGetSymbolAddress((void**)&vrth,  g_vrth);
    cudaGetSymbolAddress((void**)&attnh, g_attnh);

    cudaFuncSetAttribute(attn_f16,
                         cudaFuncAttributeMaxDynamicSharedMemorySize, ATTN_SMEM_BYTES);

    const float scale = 0.08838834764831845f;  // 1/sqrt(128)
    const size_t NW = (size_t)DIM * DIM;
    const int NT = T_LEN * DIM, NR = TR_LEN * DIM;
    const int CB = 256 * 4;

    // ---- activations -> half ----
    cvt_h<<<(NT + CB - 1) / CB, 256>>>(hs,  hsh,  NT, 1.f);
    cvt_h<<<(NR + CB - 1) / CB, 256>>>(rhs, rhsh, NR, 1.f);

    // ---- weights -> transposed half [n][k] ----
    dim3 tb(32, 8);
    dim3 tw(DIM / 32, DIM / 32);  // (48, 48)
    transpose_h<<<tw, tb>>>(Wq,  wth + 0 * NW, DIM, DIM);
    transpose_h<<<tw, tb>>>(Wk,  wth + 1 * NW, DIM, DIM);
    transpose_h<<<tw, tb>>>(Wv,  wth + 2 * NW, DIM, DIM);
    transpose_h<<<tw, tb>>>(Wkr, wth + 3 * NW, DIM, DIM);
    transpose_h<<<tw, tb>>>(Wvr, wth + 4 * NW, DIM, DIM);
    transpose_h<<<tw, tb>>>(Wo,  wth + 5 * NW, DIM, DIM);

    // ---- projections ----
    dim3 grid_main(DIM / 128, T_LEN / 128);   // (12, 32)
    dim3 grid_ref(DIM / 128, TR_LEN / 64);    // (12, 16)
    gemm_f16<4><<<grid_main, 256, GEMM_SMEM_M>>>(hsh,  wth + 0 * NW, bq,  qlin);
    gemm_f16<4><<<grid_main, 256, GEMM_SMEM_M>>>(hsh,  wth + 1 * NW, bk,  klin);
    gemm_f16<4><<<grid_main, 256, GEMM_SMEM_M>>>(hsh,  wth + 2 * NW, bv,  vlin);
    gemm_f16<2><<<grid_ref,  256, GEMM_SMEM_R>>>(rhsh, wth + 3 * NW, bkr, krlin);
    gemm_f16<2><<<grid_ref,  256, GEMM_SMEM_R>>>(rhsh, wth + 4 * NW, bvr, vrlin);

    // ---- V -> transposed half [h*DH+d][t] ----
    transpose_h<<<dim3(DIM / 32, T_LEN / 32),  tb>>>(vlin,  vth,  T_LEN,  DIM);
    transpose_h<<<dim3(DIM / 32, TR_LEN / 32), tb>>>(vrlin, vrth, TR_LEN, DIM);

    // ---- RMSNorms ----
    rmsnorm_kernel<<<T_LEN, 256>>>(qlin,  gq, qlin, qh, scale);
    rmsnorm_kernel<<<T_LEN, 256>>>(klin,  gk, klin, nullptr, 1.f);
    rmsnorm_kernel<<<TR_LEN, 256>>>(krlin, gk, nullptr, krh, 1.f);

    // ---- RoPE -> half ----
    int rope_blocks = (T_LEN * (DIM / 2) + 255) / 256;
    rope_kernel<<<rope_blocks, 256>>>(qlin, qroph, rcos, rsin, scale);
    rope_kernel<<<rope_blocks, 256>>>(klin, kh,    rcos, rsin, 1.f);

    // ---- attention: ref writes, main accumulates ----
    dim3 attn_grid(T_LEN / 64, NH);  // (64, 12)
    attn_f16<<<attn_grid, 128, ATTN_SMEM_BYTES>>>(qh,    krh, vrth, attn, TR_LEN, 0);
    attn_f16<<<attn_grid, 128, ATTN_SMEM_BYTES>>>(qroph, kh,  vth,  attn, T_LEN, 1);

    // ---- output projection ----
    cvt_h<<<(NT + CB - 1) / CB, 256>>>(attn, attnh, NT, 1.f);
    gemm_f16<4><<<grid_main, 256, GEMM_SMEM_M>>>(attnh, wth + 5 * NW, bo, out);
}

// round 7
// speedup vs baseline: 9.5372x; 1.1042x over previous
#include <cuda_runtime.h>
#include <cuda_fp16.h>
#include <math.h>

#define T_LEN 4096
#define TR_LEN 1024
#define DIM 1536
#define NH 12
#define DH 128

// ---------------- scratch (device globals; no allocation allowed) ----------------
__device__ float g_qlin[T_LEN * DIM];
__device__ float g_klin[T_LEN * DIM];
__device__ float g_vlin[T_LEN * DIM];
__device__ float g_krlin[TR_LEN * DIM];
__device__ float g_vrlin[TR_LEN * DIM];
__device__ float g_attn[T_LEN * DIM];

// fp16 buffers
__device__ __half g_hsh[T_LEN * DIM];
__device__ __half g_rhsh[TR_LEN * DIM];
__device__ __half g_wth[6 * DIM * DIM];   // Wq,Wk,Wv,Wkr,Wvr,Wo transposed [n][k]
__device__ __half g_qh[T_LEN * DIM];      // rms(q)*scale
__device__ __half g_qroph[T_LEN * DIM];   // rope(rms(q))*scale
__device__ __half g_kh[T_LEN * DIM];      // rope(rms(k))
__device__ __half g_vth[DIM * T_LEN];     // V transposed [h*DH + d][t]
__device__ __half g_krh[TR_LEN * DIM];    // rms(ref k)
__device__ __half g_vrth[DIM * TR_LEN];   // ref V transposed
__device__ __half g_attnh[T_LEN * DIM];

// ---------------- PTX helpers ----------------
__device__ __forceinline__ void mma_f16(float& c0, float& c1, float& c2, float& c3,
                                        unsigned a0, unsigned a1, unsigned a2, unsigned a3,
                                        unsigned b0, unsigned b1) {
    asm volatile(
        "mma.sync.aligned.m16n8k16.row.col.f32.f16.f16.f32 "
        "{%0,%1,%2,%3},{%4,%5,%6,%7},{%8,%9},{%0,%1,%2,%3};"
        : "+f"(c0), "+f"(c1), "+f"(c2), "+f"(c3)
        : "r"(a0), "r"(a1), "r"(a2), "r"(a3), "r"(b0), "r"(b1));
}
__device__ __forceinline__ void ldsm4(unsigned& r0, unsigned& r1, unsigned& r2, unsigned& r3,
                                      unsigned addr) {
    asm volatile("ldmatrix.sync.aligned.m8n8.x4.shared.b16 {%0,%1,%2,%3}, [%4];"
                 : "=r"(r0), "=r"(r1), "=r"(r2), "=r"(r3) : "r"(addr));
}
__device__ __forceinline__ void cp16(void* dst_smem, const void* src) {
    unsigned s = (unsigned)__cvta_generic_to_shared(dst_smem);
    asm volatile("cp.async.cg.shared.global [%0], [%1], 16;" :: "r"(s), "l"(src));
}
__device__ __forceinline__ void cp_commit() { asm volatile("cp.async.commit_group;"); }
__device__ __forceinline__ void cp_wait1()  { asm volatile("cp.async.wait_group 1;"); }
__device__ __forceinline__ void cp_wait0()  { asm volatile("cp.async.wait_group 0;"); }
__device__ __forceinline__ unsigned h2u(__half2 h) { return *(unsigned*)&h; }

// ---------------- float -> half conversion (vectorized, optional scale) ----------------
__global__ __launch_bounds__(256) void cvt_h(
    const float* __restrict__ in, __half* __restrict__ out, int n, float scale)
{
    int i4 = (blockIdx.x * 256 + threadIdx.x) * 4;
    if (i4 >= n) return;
    float4 v = *(const float4*)(in + i4);
    __half2 h0 = __float22half2_rn(make_float2(v.x * scale, v.y * scale));
    __half2 h1 = __float22half2_rn(make_float2(v.z * scale, v.w * scale));
    uint2 u; u.x = h2u(h0); u.y = h2u(h1);
    *(uint2*)(out + i4) = u;
}

// ---------------- tiled transpose: in float [R][C] -> out half [C][R] ----------------
__global__ __launch_bounds__(256) void transpose_h(
    const float* __restrict__ in, __half* __restrict__ out, int R, int C)
{
    __shared__ float t[32][33];
    int c0 = blockIdx.x * 32, r0 = blockIdx.y * 32;
    int tx = threadIdx.x, ty = threadIdx.y;   // block (32,8)
#pragma unroll
    for (int yy = 0; yy < 32; yy += 8)
        t[ty + yy][tx] = in[(size_t)(r0 + ty + yy) * C + c0 + tx];
    __syncthreads();
#pragma unroll
    for (int yy = 0; yy < 32; yy += 8)
        out[(size_t)(c0 + ty + yy) * R + r0 + tx] = __float2half_rn(t[tx][ty + yy]);
}

// ================= GEMM (fp16 mma): C[M x 1536] = A @ W + bias =================
#define GP 20   // pitch in unsigned (40 halves)

template<int MT>
__global__ __launch_bounds__(256) void gemm_f16(
    const __half* __restrict__ A, const __half* __restrict__ Wt,
    const float* __restrict__ bias, float* __restrict__ C)
{
    constexpr int TM = MT * 32;
    constexpr int OFF_A0 = 0;
    constexpr int OFF_A1 = TM * GP;
    constexpr int OFF_B0 = 2 * TM * GP;
    constexpr int OFF_B1 = OFF_B0 + 128 * GP;

    extern __shared__ unsigned smu[];
    const int bm = blockIdx.y * TM;
    const int bn = blockIdx.x * 128;
    const int tid = threadIdx.x;
    const int lane = tid & 31, warp = tid >> 5;
    const int g = lane >> 2, l = lane & 3;
    const int wm = (warp >> 2) * (MT * 16);
    const int wn = (warp & 3) * 32;

    float c[MT][4][4];
#pragma unroll
    for (int mt = 0; mt < MT; mt++)
#pragma unroll
        for (int nt = 0; nt < 4; nt++)
#pragma unroll
            for (int i = 0; i < 4; i++) c[mt][nt][i] = 0.f;

    auto issue = [&](int kt, int buf) {
        unsigned* Au = smu + (buf ? OFF_A1 : OFF_A0);
        unsigned* Bu = smu + (buf ? OFF_B1 : OFF_B0);
        const int k0 = kt * 32;
#pragma unroll
        for (int u = 0; u < MT / 2; u++) {
            int i = tid + u * 256;
            int r = i >> 2, c4 = i & 3;
            cp16(Au + r * GP + c4 * 4, A + (size_t)(bm + r) * DIM + k0 + c4 * 8);
        }
#pragma unroll
        for (int u = 0; u < 2; u++) {
            int i = tid + u * 256;
            int r = i >> 2, c4 = i & 3;
            cp16(Bu + r * GP + c4 * 4, Wt + (size_t)(bn + r) * DIM + k0 + c4 * 8);
        }
        cp_commit();
    };

    issue(0, 0);
    const int NKT = DIM / 32;  // 48
    for (int kt = 0; kt < NKT; kt++) {
        int buf = kt & 1;
        if (kt + 1 < NKT) { issue(kt + 1, buf ^ 1); cp_wait1(); }
        else              { cp_wait0(); }
        __syncthreads();

        const unsigned* As = smu + (buf ? OFF_A1 : OFF_A0);
        const unsigned* Bs = smu + (buf ? OFF_B1 : OFF_B0);

#pragma unroll
        for (int kk = 0; kk < 2; kk++) {
            unsigned a[MT][4];
#pragma unroll
            for (int mt = 0; mt < MT; mt++) {
                int row = wm + mt * 16;
                a[mt][0] = As[(row + g)     * GP + kk * 8 + l];
                a[mt][1] = As[(row + g + 8) * GP + kk * 8 + l];
                a[mt][2] = As[(row + g)     * GP + kk * 8 + l + 4];
                a[mt][3] = As[(row + g + 8) * GP + kk * 8 + l + 4];
            }
            unsigned b[4][2];
#pragma unroll
            for (int nt = 0; nt < 4; nt++) {
                int col = wn + nt * 8;
                b[nt][0] = Bs[(col + g) * GP + kk * 8 + l];
                b[nt][1] = Bs[(col + g) * GP + kk * 8 + l + 4];
            }
#pragma unroll
            for (int mt = 0; mt < MT; mt++)
#pragma unroll
                for (int nt = 0; nt < 4; nt++)
                    mma_f16(c[mt][nt][0], c[mt][nt][1], c[mt][nt][2], c[mt][nt][3],
                            a[mt][0], a[mt][1], a[mt][2], a[mt][3],
                            b[nt][0], b[nt][1]);
        }
        __syncthreads();
    }

#pragma unroll
    for (int mt = 0; mt < MT; mt++) {
#pragma unroll
        for (int nt = 0; nt < 4; nt++) {
            int row = bm + wm + mt * 16 + g;
            int col = bn + wn + nt * 8 + 2 * l;
            float b0 = bias[col], b1 = bias[col + 1];
            C[(size_t)row * DIM + col]           = c[mt][nt][0] + b0;
            C[(size_t)row * DIM + col + 1]       = c[mt][nt][1] + b1;
            C[(size_t)(row + 8) * DIM + col]     = c[mt][nt][2] + b0;
            C[(size_t)(row + 8) * DIM + col + 1] = c[mt][nt][3] + b1;
        }
    }
}

#define GEMM_SMEM_M ((4 * 128 * GP) * 4)
#define GEMM_SMEM_R ((2 * 64 * GP + 2 * 128 * GP) * 4)

// ---------------- RMSNorm: optional float out, optional half out (scaled) ----------------
__global__ __launch_bounds__(256) void rmsnorm_kernel(
    const float* __restrict__ x, const float* __restrict__ g,
    float* __restrict__ out_f, __half* __restrict__ out_b, float bscale)
{
    const int row = blockIdx.x;
    const float* xr = x + (size_t)row * DIM;
    const int tid = threadIdx.x;

    float ss = 0.f;
    for (int i = tid; i < DIM; i += 256) {
        float v = xr[i];
        ss += v * v;
    }
#pragma unroll
    for (int off = 16; off; off >>= 1) ss += __shfl_xor_sync(0xffffffffu, ss, off);

    __shared__ float wsum[8];
    __shared__ float inv_s;
    if ((tid & 31) == 0) wsum[tid >> 5] = ss;
    __syncthreads();
    if (tid == 0) {
        float t = 0.f;
#pragma unroll
        for (int w = 0; w < 8; w++) t += wsum[w];
        inv_s = rsqrtf(t / (float)DIM + 1e-6f);
    }
    __syncthreads();
    float inv = inv_s;
    for (int i = tid; i < DIM; i += 256) {
        float v = xr[i] * inv * g[i];
        if (out_f) out_f[(size_t)row * DIM + i] = v;
        if (out_b) out_b[(size_t)row * DIM + i] = __float2half_rn(v * bscale);
    }
}

// ---------------- RoPE -> half (optional scale) ----------------
__global__ __launch_bounds__(256) void rope_kernel(
    const float* __restrict__ in, __half* __restrict__ out,
    const float* __restrict__ rc, const float* __restrict__ rs, float scale)
{
    int idx = blockIdx.x * 256 + threadIdx.x;
    if (idx >= T_LEN * (DIM / 2)) return;
    int t = idx / (DIM / 2);
    int p = idx % (DIM / 2);
    int h = p >> 6;
    int i = p & 63;
    size_t base = (size_t)t * DIM + h * DH + 2 * i;
    float e = in[base];
    float o = in[base + 1];
    float c = rc[t * (DH / 2) + i];
    float s = rs[t * (DH / 2) + i];
    *(__half2*)(out + base) =
        __float22half2_rn(make_float2((e * c - o * s) * scale, (e * s + o * c) * scale));
}

// ================= Flash attention (fp16 mma + ldmatrix, register-P) =================
// grid (T_LEN/128, NH), 256 threads (8 warps); warp w owns q rows [q0+16w, +16).
// Q,K: half [t][DIM] (head slice), V: half [h*DH+d][Tk] transposed. Q pre-scaled.
// Pitches: Q,K 136 halves (68 u); V 72 halves (36 u). P lives in registers.
#define AQ 68
#define AV 36
#define AT_OFF_Q  0
#define AT_OFF_K0 (128 * AQ)
#define AT_OFF_K1 (AT_OFF_K0 + 64 * AQ)
#define AT_OFF_V0 (AT_OFF_K1 + 64 * AQ)
#define AT_OFF_V1 (AT_OFF_V0 + 128 * AV)
#define ATTN_SMEM_BYTES ((AT_OFF_V1 + 128 * AV) * 4)   // 106496 B

__global__ __launch_bounds__(256) void attn_f16(
    const __half* __restrict__ Q, const __half* __restrict__ Kp,
    const __half* __restrict__ Vt, float* __restrict__ Out,
    int Tk, int accumulate)
{
    extern __shared__ unsigned smu[];

    const int h = blockIdx.y;
    const int q0 = blockIdx.x * 128;
    const int tid = threadIdx.x;
    const int lane = tid & 31, warp = tid >> 5;
    const int g = lane >> 2, l = lane & 3;
    const unsigned sbase = (unsigned)__cvta_generic_to_shared(smu);

    // per-lane ldmatrix address components
    const int ql_row = lane & 15;
    const unsigned ql_addr = sbase + (AT_OFF_Q + (warp * 16 + ql_row) * AQ
                                      + ((lane & 16) ? 4 : 0)) * 4;
    const int bl_row  = (lane & 7) + ((lane & 16) ? 8 : 0);  // B-frag row within 16-block
    const int bl_colu = (lane & 8) ? 4 : 0;                  // k-half offset (u)

    auto issue_tile = [&](int t, int buf) {
        unsigned* Ku = smu + (buf ? AT_OFF_K1 : AT_OFF_K0);
        unsigned* Vu = smu + (buf ? AT_OFF_V1 : AT_OFF_V0);
        const size_t krow = (size_t)(t * 64) * DIM + h * DH;
#pragma unroll
        for (int u = 0; u < 4; u++) {
            int i = tid + u * 256;              // K: 64 rows x 16 cp16
            int r = i >> 4, c4 = i & 15;
            cp16(Ku + r * AQ + c4 * 4, Kp + krow + (size_t)r * DIM + c4 * 8);
        }
#pragma unroll
        for (int u = 0; u < 4; u++) {
            int i = tid + u * 256;              // V: 128 rows x 8 cp16
            int r = i >> 3, c4 = i & 7;
            cp16(Vu + r * AV + c4 * 4,
                 Vt + (size_t)(h * DH + r) * Tk + t * 64 + c4 * 8);
        }
        cp_commit();
    };

    issue_tile(0, 0);

    // Q tile fill (pre-scaled half): 128 rows x 16 cp16
#pragma unroll
    for (int u = 0; u < 8; u++) {
        int i = tid + u * 256;
        int r = i >> 4, c4 = i & 15;
        cp16(smu + AT_OFF_Q + r * AQ + c4 * 4,
             Q + (size_t)(q0 + r) * DIM + h * DH + c4 * 8);
    }
    cp_commit();

    float o[16][4];
#pragma unroll
    for (int nt = 0; nt < 16; nt++)
#pragma unroll
        for (int i = 0; i < 4; i++) o[nt][i] = 0.f;
    float m0 = -1e30f, m1 = -1e30f, l0 = 0.f, l1 = 0.f;

    unsigned qa[8][4];
    const int ntiles = Tk / 64;

    for (int t = 0; t < ntiles; t++) {
        int buf = t & 1;
        if (t + 1 < ntiles) { issue_tile(t + 1, buf ^ 1); cp_wait1(); }
        else                { cp_wait0(); }
        __syncthreads();

        if (t == 0) {
            // hoist Q fragments into registers (one-time)
#pragma unroll
            for (int kk = 0; kk < 8; kk++)
                ldsm4(qa[kk][0], qa[kk][1], qa[kk][2], qa[kk][3], ql_addr + kk * 32);
        }

        const unsigned koff = sbase + (buf ? AT_OFF_K1 : AT_OFF_K0) * 4;
        const unsigned voff = sbase + (buf ? AT_OFF_V1 : AT_OFF_V0) * 4;

        // ---- S = Q K^T ----
        float s[8][4];
#pragma unroll
        for (int nt = 0; nt < 8; nt++)
#pragma unroll
            for (int i = 0; i < 4; i++) s[nt][i] = 0.f;

#pragma unroll
        for (int kk = 0; kk < 8; kk++) {
            unsigned kb[4][4];
#pragma unroll
            for (int j = 0; j < 4; j++)
                ldsm4(kb[j][0], kb[j][1], kb[j][2], kb[j][3],
                      koff + ((j * 16 + bl_row) * AQ + kk * 8 + bl_colu) * 4);
#pragma unroll
            for (int j = 0; j < 4; j++) {
                mma_f16(s[2*j][0], s[2*j][1], s[2*j][2], s[2*j][3],
                        qa[kk][0], qa[kk][1], qa[kk][2], qa[kk][3], kb[j][0], kb[j][1]);
                mma_f16(s[2*j+1][0], s[2*j+1][1], s[2*j+1][2], s[2*j+1][3],
                        qa[kk][0], qa[kk][1], qa[kk][2], qa[kk][3], kb[j][2], kb[j][3]);
            }
        }

        // ---- online softmax (rows warp-local; quad = 4 lanes of one row) ----
        float tm0 = -1e30f, tm1 = -1e30f;
#pragma unroll
        for (int nt = 0; nt < 8; nt++) {
            tm0 = fmaxf(tm0, fmaxf(s[nt][0], s[nt][1]));
            tm1 = fmaxf(tm1, fmaxf(s[nt][2], s[nt][3]));
        }
        tm0 = fmaxf(tm0, __shfl_xor_sync(0xffffffffu, tm0, 1));
        tm0 = fmaxf(tm0, __shfl_xor_sync(0xffffffffu, tm0, 2));
        tm1 = fmaxf(tm1, __shfl_xor_sync(0xffffffffu, tm1, 1));
        tm1 = fmaxf(tm1, __shfl_xor_sync(0xffffffffu, tm1, 2));
        float mn0 = fmaxf(m0, tm0), mn1 = fmaxf(m1, tm1);
        float al0 = __expf(m0 - mn0), al1 = __expf(m1 - mn1);
        m0 = mn0; m1 = mn1;

        // P fragments in registers: C-fragment layout == A-fragment layout
        unsigned pa[4][4];
        float sum0 = 0.f, sum1 = 0.f;
#pragma unroll
        for (int nt = 0; nt < 8; nt++) {
            float p0 = __expf(s[nt][0] - mn0);
            float p1 = __expf(s[nt][1] - mn0);
            float p2 = __expf(s[nt][2] - mn1);
            float p3 = __expf(s[nt][3] - mn1);
            sum0 += p0 + p1;
            sum1 += p2 + p3;
            unsigned lo = h2u(__float22half2_rn(make_float2(p0, p1)));
            unsigned hi = h2u(__float22half2_rn(make_float2(p2, p3)));
            int kt = nt >> 1;
            if ((nt & 1) == 0) { pa[kt][0] = lo; pa[kt][1] = hi; }
            else               { pa[kt][2] = lo; pa[kt][3] = hi; }
        }
        sum0 += __shfl_xor_sync(0xffffffffu, sum0, 1);
        sum0 += __shfl_xor_sync(0xffffffffu, sum0, 2);
        sum1 += __shfl_xor_sync(0xffffffffu, sum1, 1);
        sum1 += __shfl_xor_sync(0xffffffffu, sum1, 2);
        l0 = l0 * al0 + sum0;
        l1 = l1 * al1 + sum1;
#pragma unroll
        for (int nt = 0; nt < 16; nt++) {
            o[nt][0] *= al0; o[nt][1] *= al0;
            o[nt][2] *= al1; o[nt][3] *= al1;
        }

        // ---- O += P @ V ----
#pragma unroll
        for (int kt = 0; kt < 4; kt++) {
            unsigned vb[8][4];
#pragma unroll
            for (int j = 0; j < 8; j++)
                ldsm4(vb[j][0], vb[j][1], vb[j][2], vb[j][3],
                      voff + ((j * 16 + bl_row) * AV + kt * 8 + bl_colu) * 4);
#pragma unroll
            for (int j = 0; j < 8; j++) {
                mma_f16(o[2*j][0], o[2*j][1], o[2*j][2], o[2*j][3],
                        pa[kt][0], pa[kt][1], pa[kt][2], pa[kt][3], vb[j][0], vb[j][1]);
                mma_f16(o[2*j+1][0], o[2*j+1][1], o[2*j+1][2], o[2*j+1][3],
                        pa[kt][0], pa[kt][1], pa[kt][2], pa[kt][3], vb[j][2], vb[j][3]);
            }
        }
        __syncthreads();
    }

    // ---- epilogue ----
    float inv0 = 1.f / l0, inv1 = 1.f / l1;
    int row0 = q0 + warp * 16 + g;
    int row1 = row0 + 8;
    if (accumulate) {
#pragma unroll
        for (int nt = 0; nt < 16; nt++) {
            int col = h * DH + nt * 8 + 2 * l;
            size_t i0 = (size_t)row0 * DIM + col;
            size_t i1 = (size_t)row1 * DIM + col;
            Out[i0]     += o[nt][0] * inv0;
            Out[i0 + 1] += o[nt][1] * inv0;
            Out[i1]     += o[nt][2] * inv1;
            Out[i1 + 1] += o[nt][3] * inv1;
        }
    } else {
#pragma unroll
        for (int nt = 0; nt < 16; nt++) {
            int col = h * DH + nt * 8 + 2 * l;
            size_t i0 = (size_t)row0 * DIM + col;
            size_t i1 = (size_t)row1 * DIM + col;
            Out[i0]     = o[nt][0] * inv0;
            Out[i0 + 1] = o[nt][1] * inv0;
            Out[i1]     = o[nt][2] * inv1;
            Out[i1 + 1] = o[nt][3] * inv1;
        }
    }
}

// ---------------- launch ----------------
extern "C" void kernel_launch(void* const* d_in, const int* in_sizes, int n_in,
                              void* d_out, int out_size)
{
    const float* hs   = (const float*)d_in[0];
    const float* rhs  = (const float*)d_in[1];
    const float* rcos = (const float*)d_in[2];
    const float* rsin = (const float*)d_in[3];
    const float* Wq   = (const float*)d_in[4];
    const float* bq   = (const float*)d_in[5];
    const float* Wk   = (const float*)d_in[6];
    const float* bk   = (const float*)d_in[7];
    const float* Wv   = (const float*)d_in[8];
    const float* bv   = (const float*)d_in[9];
    const float* Wkr  = (const float*)d_in[10];
    const float* bkr  = (const float*)d_in[11];
    const float* Wvr  = (const float*)d_in[12];
    const float* bvr  = (const float*)d_in[13];
    const float* Wo   = (const float*)d_in[14];
    const float* bo   = (const float*)d_in[15];
    const float* gq   = (const float*)d_in[16];
    const float* gk   = (const float*)d_in[17];
    float* out = (float*)d_out;

    float *qlin, *klin, *vlin, *krlin, *vrlin, *attn;
    __half *hsh, *rhsh, *wth, *qh, *qroph, *kh, *vth, *krh, *vrth, *attnh;
    cudaGetSymbolAddress((void**)&qlin,  g_qlin);
    cudaGetSymbolAddress((void**)&klin,  g_klin);
    cudaGetSymbolAddress((void**)&vlin,  g_vlin);
    cudaGetSymbolAddress((void**)&krlin, g_krlin);
    cudaGetSymbolAddress((void**)&vrlin, g_vrlin);
    cudaGetSymbolAddress((void**)&attn,  g_attn);
    cudaGetSymbolAddress((void**)&hsh,   g_hsh);
    cudaGetSymbolAddress((void**)&rhsh,  g_rhsh);
    cudaGetSymbolAddress((void**)&wth,   g_wth);
    cudaGetSymbolAddress((void**)&qh,    g_qh);
    cudaGetSymbolAddress((void**)&qroph, g_qroph);
    cudaGetSymbolAddress((void**)&kh,    g_kh);
    cudaGetSymbolAddress((void**)&vth,   g_vth);
    cudaGetSymbolAddress((void**)&krh,   g_krh);
    cudaGetSymbolAddress((void**)&vrth,  g_vrth);
    cudaGetSymbolAddress((void**)&attnh, g_attnh);

    cudaFuncSetAttribute(attn_f16,
                         cudaFuncAttributeMaxDynamicSharedMemorySize, ATTN_SMEM_BYTES);

    const float scale = 0.08838834764831845f;  // 1/sqrt(128)
    const size_t NW = (size_t)DIM * DIM;
    const int NT = T_LEN * DIM, NR = TR_LEN * DIM;
    const int CB = 256 * 4;

    // ---- activations -> half ----
    cvt_h<<<(NT + CB - 1) / CB, 256>>>(hs,  hsh,  NT, 1.f);
    cvt_h<<<(NR + CB - 1) / CB, 256>>>(rhs, rhsh, NR, 1.f);

    // ---- weights -> transposed half [n][k] ----
    dim3 tb(32, 8);
    dim3 tw(DIM / 32, DIM / 32);  // (48, 48)
    transpose_h<<<tw, tb>>>(Wq,  wth + 0 * NW, DIM, DIM);
    transpose_h<<<tw, tb>>>(Wk,  wth + 1 * NW, DIM, DIM);
    transpose_h<<<tw, tb>>>(Wv,  wth + 2 * NW, DIM, DIM);
    transpose_h<<<tw, tb>>>(Wkr, wth + 3 * NW, DIM, DIM);
    transpose_h<<<tw, tb>>>(Wvr, wth + 4 * NW, DIM, DIM);
    transpose_h<<<tw, tb>>>(Wo,  wth + 5 * NW, DIM, DIM);

    // ---- projections ----
    dim3 grid_main(DIM / 128, T_LEN / 128);   // (12, 32)
    dim3 grid_ref(DIM / 128, TR_LEN / 64);    // (12, 16)
    gemm_f16<4><<<grid_main, 256, GEMM_SMEM_M>>>(hsh,  wth + 0 * NW, bq,  qlin);
    gemm_f16<4><<<grid_main, 256, GEMM_SMEM_M>>>(hsh,  wth + 1 * NW, bk,  klin);
    gemm_f16<4><<<grid_main, 256, GEMM_SMEM_M>>>(hsh,  wth + 2 * NW, bv,  vlin);
    gemm_f16<2><<<grid_ref,  256, GEMM_SMEM_R>>>(rhsh, wth + 3 * NW, bkr, krlin);
    gemm_f16<2><<<grid_ref,  256, GEMM_SMEM_R>>>(rhsh, wth + 4 * NW, bvr, vrlin);

    // ---- V -> transposed half [h*DH+d][t] ----
    transpose_h<<<dim3(DIM / 32, T_LEN / 32),  tb>>>(vlin,  vth,  T_LEN,  DIM);
    transpose_h<<<dim3(DIM / 32, TR_LEN / 32), tb>>>(vrlin, vrth, TR_LEN, DIM);

    // ---- RMSNorms ----
    rmsnorm_kernel<<<T_LEN, 256>>>(qlin,  gq, qlin, qh, scale);
    rmsnorm_kernel<<<T_LEN, 256>>>(klin,  gk, klin, nullptr, 1.f);
    rmsnorm_kernel<<<TR_LEN, 256>>>(krlin, gk, nullptr, krh, 1.f);

    // ---- RoPE -> half ----
    int rope_blocks = (T_LEN * (DIM / 2) + 255) / 256;
    rope_kernel<<<rope_blocks, 256>>>(qlin, qroph, rcos, rsin, scale);
    rope_kernel<<<rope_blocks, 256>>>(klin, kh,    rcos, rsin, 1.f);

    // ---- attention: ref writes, main accumulates ----
    dim3 attn_grid(T_LEN / 128, NH);  // (32, 12)
    attn_f16<<<attn_grid, 256, ATTN_SMEM_BYTES>>>(qh,    krh, vrth, attn, TR_LEN, 0);
    attn_f16<<<attn_grid, 256, ATTN_SMEM_BYTES>>>(qroph, kh,  vth,  attn, T_LEN, 1);

    // ---- output projection ----
    cvt_h<<<(NT + CB - 1) / CB, 256>>>(attn, attnh, NT, 1.f);
    gemm_f16<4><<<grid_main, 256, GEMM_SMEM_M>>>(attnh, wth + 5 * NW, bo, out);
}

// round 8
// speedup vs baseline: 10.5196x; 1.1030x over previous
#include <cuda_runtime.h>
#include <cuda_fp16.h>
#include <math.h>

#define T_LEN 4096
#define TR_LEN 1024
#define DIM 1536
#define NH 12
#define DH 128

// ---------------- scratch (device globals; no allocation allowed) ----------------
__device__ float g_qlin[T_LEN * DIM];
__device__ float g_klin[T_LEN * DIM];
__device__ float g_vlin[T_LEN * DIM];
__device__ float g_krlin[TR_LEN * DIM];
__device__ float g_vrlin[TR_LEN * DIM];

__device__ __half g_hsh[T_LEN * DIM];
__device__ __half g_rhsh[TR_LEN * DIM];
__device__ __half g_wth[6 * DIM * DIM];   // Wq,Wk,Wv,Wkr,Wvr,Wo transposed [n][k]
__device__ __half g_qh[T_LEN * DIM];      // rms(q)*scale
__device__ __half g_qroph[T_LEN * DIM];   // rope(rms(q))*scale
__device__ __half g_kh[T_LEN * DIM];      // rope(rms(k))
__device__ __half g_vth[DIM * T_LEN];     // V transposed [h*DH + d][t]
__device__ __half g_krh[TR_LEN * DIM];    // rms(ref k)
__device__ __half g_vrth[DIM * TR_LEN];   // ref V transposed
__device__ __half g_attnh[T_LEN * DIM];   // attention output (half, fused ref+main)

// ---------------- PTX helpers ----------------
__device__ __forceinline__ void mma_f16(float& c0, float& c1, float& c2, float& c3,
                                        unsigned a0, unsigned a1, unsigned a2, unsigned a3,
                                        unsigned b0, unsigned b1) {
    asm volatile(
        "mma.sync.aligned.m16n8k16.row.col.f32.f16.f16.f32 "
        "{%0,%1,%2,%3},{%4,%5,%6,%7},{%8,%9},{%0,%1,%2,%3};"
        : "+f"(c0), "+f"(c1), "+f"(c2), "+f"(c3)
        : "r"(a0), "r"(a1), "r"(a2), "r"(a3), "r"(b0), "r"(b1));
}
__device__ __forceinline__ void ldsm4(unsigned& r0, unsigned& r1, unsigned& r2, unsigned& r3,
                                      unsigned addr) {
    asm volatile("ldmatrix.sync.aligned.m8n8.x4.shared.b16 {%0,%1,%2,%3}, [%4];"
                 : "=r"(r0), "=r"(r1), "=r"(r2), "=r"(r3) : "r"(addr));
}
__device__ __forceinline__ void cp16(void* dst_smem, const void* src) {
    unsigned s = (unsigned)__cvta_generic_to_shared(dst_smem);
    asm volatile("cp.async.cg.shared.global [%0], [%1], 16;" :: "r"(s), "l"(src));
}
__device__ __forceinline__ void cp_commit() { asm volatile("cp.async.commit_group;"); }
__device__ __forceinline__ void cp_wait0()  { asm volatile("cp.async.wait_group 0;"); }
__device__ __forceinline__ unsigned h2u(__half2 h) { return *(unsigned*)&h; }

// ---------------- float -> half conversion ----------------
__global__ __launch_bounds__(256) void cvt_h(
    const float* __restrict__ in, __half* __restrict__ out, int n, float scale)
{
    int i4 = (blockIdx.x * 256 + threadIdx.x) * 4;
    if (i4 >= n) return;
    float4 v = *(const float4*)(in + i4);
    __half2 h0 = __float22half2_rn(make_float2(v.x * scale, v.y * scale));
    __half2 h1 = __float22half2_rn(make_float2(v.z * scale, v.w * scale));
    uint2 u; u.x = h2u(h0); u.y = h2u(h1);
    *(uint2*)(out + i4) = u;
}

// ---------------- tiled transpose: float [R][C] -> half [C][R] ----------------
__global__ __launch_bounds__(256) void transpose_h(
    const float* __restrict__ in, __half* __restrict__ out, int R, int C)
{
    __shared__ float t[32][33];
    int c0 = blockIdx.x * 32, r0 = blockIdx.y * 32;
    int tx = threadIdx.x, ty = threadIdx.y;
#pragma unroll
    for (int yy = 0; yy < 32; yy += 8)
        t[ty + yy][tx] = in[(size_t)(r0 + ty + yy) * C + c0 + tx];
    __syncthreads();
#pragma unroll
    for (int yy = 0; yy < 32; yy += 8)
        out[(size_t)(c0 + ty + yy) * R + r0 + tx] = __float2half_rn(t[tx][ty + yy]);
}

// 6 weight transposes in one launch (z picks the matrix)
struct Src6 { const float* p[6]; };
__global__ __launch_bounds__(256) void transpose6_h(Src6 s, __half* __restrict__ dstbase)
{
    __shared__ float t[32][33];
    const float* in = s.p[blockIdx.z];
    __half* out = dstbase + (size_t)blockIdx.z * DIM * DIM;
    int c0 = blockIdx.x * 32, r0 = blockIdx.y * 32;
    int tx = threadIdx.x, ty = threadIdx.y;
#pragma unroll
    for (int yy = 0; yy < 32; yy += 8)
        t[ty + yy][tx] = in[(size_t)(r0 + ty + yy) * DIM + c0 + tx];
    __syncthreads();
#pragma unroll
    for (int yy = 0; yy < 32; yy += 8)
        out[(size_t)(c0 + ty + yy) * DIM + r0 + tx] = __float2half_rn(t[tx][ty + yy]);
}

// ================= GEMM (fp16 mma), up to 3 outputs per launch =================
#define GP 20   // smem pitch in unsigned (40 halves)
struct Gemm3 { const __half* W[3]; const float* b[3]; float* C[3]; };

template<int MT>
__global__ __launch_bounds__(256) void gemm_f16_multi(
    const __half* __restrict__ A, Gemm3 p)
{
    constexpr int TM = MT * 32;
    constexpr int OFF_A0 = 0;
    constexpr int OFF_A1 = TM * GP;
    constexpr int OFF_B0 = 2 * TM * GP;
    constexpr int OFF_B1 = OFF_B0 + 128 * GP;

    extern __shared__ unsigned smu[];
    const int which = blockIdx.x / 12;
    const __half* Wt = p.W[which];
    const float* bias = p.b[which];
    float* C = p.C[which];

    const int bm = blockIdx.y * TM;
    const int bn = (blockIdx.x % 12) * 128;
    const int tid = threadIdx.x;
    const int lane = tid & 31, warp = tid >> 5;
    const int g = lane >> 2, l = lane & 3;
    const int wm = (warp >> 2) * (MT * 16);
    const int wn = (warp & 3) * 32;

    float c[MT][4][4];
#pragma unroll
    for (int mt = 0; mt < MT; mt++)
#pragma unroll
        for (int nt = 0; nt < 4; nt++)
#pragma unroll
            for (int i = 0; i < 4; i++) c[mt][nt][i] = 0.f;

    auto issue = [&](int kt, int buf) {
        unsigned* Au = smu + (buf ? OFF_A1 : OFF_A0);
        unsigned* Bu = smu + (buf ? OFF_B1 : OFF_B0);
        const int k0 = kt * 32;
#pragma unroll
        for (int u = 0; u < MT / 2; u++) {
            int i = tid + u * 256;
            int r = i >> 2, c4 = i & 3;
            cp16(Au + r * GP + c4 * 4, A + (size_t)(bm + r) * DIM + k0 + c4 * 8);
        }
#pragma unroll
        for (int u = 0; u < 2; u++) {
            int i = tid + u * 256;
            int r = i >> 2, c4 = i & 3;
            cp16(Bu + r * GP + c4 * 4, Wt + (size_t)(bn + r) * DIM + k0 + c4 * 8);
        }
        cp_commit();
    };

    issue(0, 0);
    const int NKT = DIM / 32;  // 48
    for (int kt = 0; kt < NKT; kt++) {
        int buf = kt & 1;
        cp_wait0();
        __syncthreads();                       // all warps done with buf^1 before refill
        if (kt + 1 < NKT) issue(kt + 1, buf ^ 1);

        const unsigned* As = smu + (buf ? OFF_A1 : OFF_A0);
        const unsigned* Bs = smu + (buf ? OFF_B1 : OFF_B0);

#pragma unroll
        for (int kk = 0; kk < 2; kk++) {
            unsigned a[MT][4];
#pragma unroll
            for (int mt = 0; mt < MT; mt++) {
                int row = wm + mt * 16;
                a[mt][0] = As[(row + g)     * GP + kk * 8 + l];
                a[mt][1] = As[(row + g + 8) * GP + kk * 8 + l];
                a[mt][2] = As[(row + g)     * GP + kk * 8 + l + 4];
                a[mt][3] = As[(row + g + 8) * GP + kk * 8 + l + 4];
            }
            unsigned b[4][2];
#pragma unroll
            for (int nt = 0; nt < 4; nt++) {
                int col = wn + nt * 8;
                b[nt][0] = Bs[(col + g) * GP + kk * 8 + l];
                b[nt][1] = Bs[(col + g) * GP + kk * 8 + l + 4];
            }
#pragma unroll
            for (int mt = 0; mt < MT; mt++)
#pragma unroll
                for (int nt = 0; nt < 4; nt++)
                    mma_f16(c[mt][nt][0], c[mt][nt][1], c[mt][nt][2], c[mt][nt][3],
                            a[mt][0], a[mt][1], a[mt][2], a[mt][3],
                            b[nt][0], b[nt][1]);
        }
    }

#pragma unroll
    for (int mt = 0; mt < MT; mt++) {
#pragma unroll
        for (int nt = 0; nt < 4; nt++) {
            int row = bm + wm + mt * 16 + g;
            int col = bn + wn + nt * 8 + 2 * l;
            float b0 = bias[col], b1 = bias[col + 1];
            C[(size_t)row * DIM + col]           = c[mt][nt][0] + b0;
            C[(size_t)row * DIM + col + 1]       = c[mt][nt][1] + b1;
            C[(size_t)(row + 8) * DIM + col]     = c[mt][nt][2] + b0;
            C[(size_t)(row + 8) * DIM + col + 1] = c[mt][nt][3] + b1;
        }
    }
}

#define GEMM_SMEM_M ((4 * 128 * GP) * 4)
#define GEMM_SMEM_R ((2 * 64 * GP + 2 * 128 * GP) * 4)

// ---------------- RMSNorm ----------------
__global__ __launch_bounds__(256) void rmsnorm_kernel(
    const float* __restrict__ x, const float* __restrict__ g,
    float* __restrict__ out_f, __half* __restrict__ out_b, float bscale)
{
    const int row = blockIdx.x;
    const float* xr = x + (size_t)row * DIM;
    const int tid = threadIdx.x;

    float ss = 0.f;
    for (int i = tid; i < DIM; i += 256) {
        float v = xr[i];
        ss += v * v;
    }
#pragma unroll
    for (int off = 16; off; off >>= 1) ss += __shfl_xor_sync(0xffffffffu, ss, off);

    __shared__ float wsum[8];
    __shared__ float inv_s;
    if ((tid & 31) == 0) wsum[tid >> 5] = ss;
    __syncthreads();
    if (tid == 0) {
        float t = 0.f;
#pragma unroll
        for (int w = 0; w < 8; w++) t += wsum[w];
        inv_s = rsqrtf(t / (float)DIM + 1e-6f);
    }
    __syncthreads();
    float inv = inv_s;
    for (int i = tid; i < DIM; i += 256) {
        float v = xr[i] * inv * g[i];
        if (out_f) out_f[(size_t)row * DIM + i] = v;
        if (out_b) out_b[(size_t)row * DIM + i] = __float2half_rn(v * bscale);
    }
}

// ---------------- RoPE -> half ----------------
__global__ __launch_bounds__(256) void rope_kernel(
    const float* __restrict__ in, __half* __restrict__ out,
    const float* __restrict__ rc, const float* __restrict__ rs, float scale)
{
    int idx = blockIdx.x * 256 + threadIdx.x;
    if (idx >= T_LEN * (DIM / 2)) return;
    int t = idx / (DIM / 2);
    int p = idx % (DIM / 2);
    int h = p >> 6;
    int i = p & 63;
    size_t base = (size_t)t * DIM + h * DH + 2 * i;
    float e = in[base];
    float o = in[base + 1];
    float c = rc[t * (DH / 2) + i];
    float s = rs[t * (DH / 2) + i];
    *(__half2*)(out + base) =
        __float22half2_rn(make_float2((e * c - o * s) * scale, (e * s + o * c) * scale));
}

// ================= Fused flash attention (ref + main in one kernel) =================
// grid (T_LEN/128, NH), 256 threads (8 warps); warp w owns q rows [q0+16w, +16).
// 128-key memory tiles (double buffered), two 64-key compute subtiles per tile.
// Phase 0: ref attention -> normalized result stashed in registers as half2.
// Phase 1: main attention -> sum written directly as half to Outh.
#define AQ 68   // pitch in unsigned for Q,K (key-rows) and V (d-rows, 128-key cols)
#define ATT_Q  0
#define ATT_K0 (128 * AQ)
#define ATT_K1 (ATT_K0 + 128 * AQ)
#define ATT_V0 (ATT_K1 + 128 * AQ)
#define ATT_V1 (ATT_V0 + 128 * AQ)
#define ATT_SMEM ((ATT_V1 + 128 * AQ) * 4)   // 174080 B

__global__ __launch_bounds__(256) void attn_fused(
    const __half* __restrict__ Q0, const __half* __restrict__ K0p,
    const __half* __restrict__ V0p, int Tk0,
    const __half* __restrict__ Q1, const __half* __restrict__ K1p,
    const __half* __restrict__ V1p, int Tk1,
    __half* __restrict__ Outh)
{
    extern __shared__ unsigned smu[];

    const int h = blockIdx.y;
    const int q0 = blockIdx.x * 128;
    const int tid = threadIdx.x;
    const int lane = tid & 31, warp = tid >> 5;
    const int g = lane >> 2, l = lane & 3;
    const unsigned sbase = (unsigned)__cvta_generic_to_shared(smu);

    const int ql_row = lane & 15;
    const unsigned ql_addr = sbase + (ATT_Q + (warp * 16 + ql_row) * AQ
                                      + ((lane & 16) ? 4 : 0)) * 4;
    const int bl_row  = (lane & 7) + ((lane & 16) ? 8 : 0);
    const int bl_colu = (lane & 8) ? 4 : 0;

    auto issue_Q = [&](const __half* Qp) {
#pragma unroll
        for (int u = 0; u < 8; u++) {
            int i = tid + u * 256;
            int r = i >> 4, c4 = i & 15;
            cp16(smu + ATT_Q + r * AQ + c4 * 4,
                 Qp + (size_t)(q0 + r) * DIM + h * DH + c4 * 8);
        }
    };
    auto issue_tile = [&](const __half* Kp, const __half* Vt, int Tk, int t, int buf) {
        unsigned* Ku = smu + (buf ? ATT_K1 : ATT_K0);
        unsigned* Vu = smu + (buf ? ATT_V1 : ATT_V0);
        const size_t krow = (size_t)(t * 128) * DIM + h * DH;
#pragma unroll
        for (int u = 0; u < 8; u++) {
            int i = tid + u * 256;              // K: 128 key-rows x 16 cp16
            int r = i >> 4, c4 = i & 15;
            cp16(Ku + r * AQ + c4 * 4, Kp + krow + (size_t)r * DIM + c4 * 8);
        }
#pragma unroll
        for (int u = 0; u < 8; u++) {
            int i = tid + u * 256;              // V: 128 d-rows x 16 cp16 (128 keys)
            int r = i >> 4, c4 = i & 15;
            cp16(Vu + r * AQ + c4 * 4,
                 Vt + (size_t)(h * DH + r) * Tk + t * 128 + c4 * 8);
        }
        cp_commit();
    };

    float o[16][4];
    float m0, m1, l0, l1;
    unsigned qa[8][4];
    unsigned stash[16][2];

#pragma unroll
    for (int ph = 0; ph < 2; ph++) {
        const __half* Qp = ph ? Q1 : Q0;
        const __half* Kp = ph ? K1p : K0p;
        const __half* Vp = ph ? V1p : V0p;
        const int Tk = ph ? Tk1 : Tk0;
        const int ntiles = Tk / 128;

#pragma unroll
        for (int nt = 0; nt < 16; nt++)
#pragma unroll
            for (int i = 0; i < 4; i++) o[nt][i] = 0.f;
        m0 = m1 = -1e30f;
        l0 = l1 = 0.f;

        issue_Q(Qp);                 // same cp group as tile 0
        issue_tile(Kp, Vp, Tk, 0, 0);

        for (int t = 0; t < ntiles; t++) {
            int buf = t & 1;
            cp_wait0();
            __syncthreads();         // all warps done with buf^1 before refill
            if (t + 1 < ntiles) issue_tile(Kp, Vp, Tk, t + 1, buf ^ 1);

            if (t == 0) {
#pragma unroll
                for (int kk = 0; kk < 8; kk++)
                    ldsm4(qa[kk][0], qa[kk][1], qa[kk][2], qa[kk][3], ql_addr + kk * 32);
            }

            const unsigned koff = sbase + (buf ? ATT_K1 : ATT_K0) * 4;
            const unsigned voff = sbase + (buf ? ATT_V1 : ATT_V0) * 4;

#pragma unroll
            for (int st = 0; st < 2; st++) {
                // ---- S = Q K^T over 64-key subtile ----
                float s[8][4];
#pragma unroll
                for (int nt = 0; nt < 8; nt++)
#pragma unroll
                    for (int i = 0; i < 4; i++) s[nt][i] = 0.f;

#pragma unroll
                for (int kk = 0; kk < 8; kk++) {
                    unsigned kb[4][4];
#pragma unroll
                    for (int j = 0; j < 4; j++)
                        ldsm4(kb[j][0], kb[j][1], kb[j][2], kb[j][3],
                              koff + ((st * 64 + j * 16 + bl_row) * AQ + kk * 8 + bl_colu) * 4);
#pragma unroll
                    for (int j = 0; j < 4; j++) {
                        mma_f16(s[2*j][0], s[2*j][1], s[2*j][2], s[2*j][3],
                                qa[kk][0], qa[kk][1], qa[kk][2], qa[kk][3], kb[j][0], kb[j][1]);
                        mma_f16(s[2*j+1][0], s[2*j+1][1], s[2*j+1][2], s[2*j+1][3],
                                qa[kk][0], qa[kk][1], qa[kk][2], qa[kk][3], kb[j][2], kb[j][3]);
                    }
                }

                // ---- online softmax ----
                float tm0 = -1e30f, tm1 = -1e30f;
#pragma unroll
                for (int nt = 0; nt < 8; nt++) {
                    tm0 = fmaxf(tm0, fmaxf(s[nt][0], s[nt][1]));
                    tm1 = fmaxf(tm1, fmaxf(s[nt][2], s[nt][3]));
                }
                tm0 = fmaxf(tm0, __shfl_xor_sync(0xffffffffu, tm0, 1));
                tm0 = fmaxf(tm0, __shfl_xor_sync(0xffffffffu, tm0, 2));
                tm1 = fmaxf(tm1, __shfl_xor_sync(0xffffffffu, tm1, 1));
                tm1 = fmaxf(tm1, __shfl_xor_sync(0xffffffffu, tm1, 2));
                float mn0 = fmaxf(m0, tm0), mn1 = fmaxf(m1, tm1);
                float al0 = __expf(m0 - mn0), al1 = __expf(m1 - mn1);
                m0 = mn0; m1 = mn1;

                unsigned pa[4][4];
                float sum0 = 0.f, sum1 = 0.f;
#pragma unroll
                for (int nt = 0; nt < 8; nt++) {
                    float p0 = __expf(s[nt][0] - mn0);
                    float p1 = __expf(s[nt][1] - mn0);
                    float p2 = __expf(s[nt][2] - mn1);
                    float p3 = __expf(s[nt][3] - mn1);
                    sum0 += p0 + p1;
                    sum1 += p2 + p3;
                    unsigned lo = h2u(__float22half2_rn(make_float2(p0, p1)));
                    unsigned hi = h2u(__float22half2_rn(make_float2(p2, p3)));
                    int kt = nt >> 1;
                    if ((nt & 1) == 0) { pa[kt][0] = lo; pa[kt][1] = hi; }
                    else               { pa[kt][2] = lo; pa[kt][3] = hi; }
                }
                sum0 += __shfl_xor_sync(0xffffffffu, sum0, 1);
                sum0 += __shfl_xor_sync(0xffffffffu, sum0, 2);
                sum1 += __shfl_xor_sync(0xffffffffu, sum1, 1);
                sum1 += __shfl_xor_sync(0xffffffffu, sum1, 2);
                l0 = l0 * al0 + sum0;
                l1 = l1 * al1 + sum1;
#pragma unroll
                for (int nt = 0; nt < 16; nt++) {
                    o[nt][0] *= al0; o[nt][1] *= al0;
                    o[nt][2] *= al1; o[nt][3] *= al1;
                }

                // ---- O += P @ V ----
#pragma unroll
                for (int kt = 0; kt < 4; kt++) {
                    unsigned vb[8][4];
#pragma unroll
                    for (int j = 0; j < 8; j++)
                        ldsm4(vb[j][0], vb[j][1], vb[j][2], vb[j][3],
                              voff + ((j * 16 + bl_row) * AQ + st * 32 + kt * 8 + bl_colu) * 4);
#pragma unroll
                    for (int j = 0; j < 8; j++) {
                        mma_f16(o[2*j][0], o[2*j][1], o[2*j][2], o[2*j][3],
                                pa[kt][0], pa[kt][1], pa[kt][2], pa[kt][3], vb[j][0], vb[j][1]);
                        mma_f16(o[2*j+1][0], o[2*j+1][1], o[2*j+1][2], o[2*j+1][3],
                                pa[kt][0], pa[kt][1], pa[kt][2], pa[kt][3], vb[j][2], vb[j][3]);
                    }
                }
            }
        }

        if (ph == 0) {
            float inv0 = 1.f / l0, inv1 = 1.f / l1;
#pragma unroll
            for (int nt = 0; nt < 16; nt++) {
                stash[nt][0] = h2u(__float22half2_rn(
                    make_float2(o[nt][0] * inv0, o[nt][1] * inv0)));
                stash[nt][1] = h2u(__float22half2_rn(
                    make_float2(o[nt][2] * inv1, o[nt][3] * inv1)));
            }
        }
    }

    // ---- epilogue: out = ref(stash) + main, write half ----
    float inv0 = 1.f / l0, inv1 = 1.f / l1;
    int row0 = q0 + warp * 16 + g;
    int row1 = row0 + 8;
#pragma unroll
    for (int nt = 0; nt < 16; nt++) {
        int col = h * DH + nt * 8 + 2 * l;
        float2 r0 = __half22float2(*(__half2*)&stash[nt][0]);
        float2 r1 = __half22float2(*(__half2*)&stash[nt][1]);
        __half2 w0 = __float22half2_rn(
            make_float2(r0.x + o[nt][0] * inv0, r0.y + o[nt][1] * inv0));
        __half2 w1 = __float22half2_rn(
            make_float2(r1.x + o[nt][2] * inv1, r1.y + o[nt][3] * inv1));
        *(__half2*)(Outh + (size_t)row0 * DIM + col) = w0;
        *(__half2*)(Outh + (size_t)row1 * DIM + col) = w1;
    }
}

// ---------------- launch ----------------
extern "C" void kernel_launch(void* const* d_in, const int* in_sizes, int n_in,
                              void* d_out, int out_size)
{
    const float* hs   = (const float*)d_in[0];
    const float* rhs  = (const float*)d_in[1];
    const float* rcos = (const float*)d_in[2];
    const float* rsin = (const float*)d_in[3];
    const float* Wq   = (const float*)d_in[4];
    const float* bq   = (const float*)d_in[5];
    const float* Wk   = (const float*)d_in[6];
    const float* bk   = (const float*)d_in[7];
    const float* Wv   = (const float*)d_in[8];
    const float* bv   = (const float*)d_in[9];
    const float* Wkr  = (const float*)d_in[10];
    const float* bkr  = (const float*)d_in[11];
    const float* Wvr  = (const float*)d_in[12];
    const float* bvr  = (const float*)d_in[13];
    const float* Wo   = (const float*)d_in[14];
    const float* bo   = (const float*)d_in[15];
    const float* gq   = (const float*)d_in[16];
    const float* gk   = (const float*)d_in[17];
    float* out = (float*)d_out;

    float *qlin, *klin, *vlin, *krlin, *vrlin;
    __half *hsh, *rhsh, *wth, *qh, *qroph, *kh, *vth, *krh, *vrth, *attnh;
    cudaGetSymbolAddress((void**)&qlin,  g_qlin);
    cudaGetSymbolAddress((void**)&klin,  g_klin);
    cudaGetSymbolAddress((void**)&vlin,  g_vlin);
    cudaGetSymbolAddress((void**)&krlin, g_krlin);
    cudaGetSymbolAddress((void**)&vrlin, g_vrlin);
    cudaGetSymbolAddress((void**)&hsh,   g_hsh);
    cudaGetSymbolAddress((void**)&rhsh,  g_rhsh);
    cudaGetSymbolAddress((void**)&wth,   g_wth);
    cudaGetSymbolAddress((void**)&qh,    g_qh);
    cudaGetSymbolAddress((void**)&qroph, g_qroph);
    cudaGetSymbolAddress((void**)&kh,    g_kh);
    cudaGetSymbolAddress((void**)&vth,   g_vth);
    cudaGetSymbolAddress((void**)&krh,   g_krh);
    cudaGetSymbolAddress((void**)&vrth,  g_vrth);
    cudaGetSymbolAddress((void**)&attnh, g_attnh);

    cudaFuncSetAttribute(attn_fused,
                         cudaFuncAttributeMaxDynamicSharedMemorySize, ATT_SMEM);

    const float scale = 0.08838834764831845f;  // 1/sqrt(128)
    const size_t NW = (size_t)DIM * DIM;
    const int NT = T_LEN * DIM, NR = TR_LEN * DIM;
    const int CB = 256 * 4;

    // ---- activations -> half ----
    cvt_h<<<(NT + CB - 1) / CB, 256>>>(hs,  hsh,  NT, 1.f);
    cvt_h<<<(NR + CB - 1) / CB, 256>>>(rhs, rhsh, NR, 1.f);

    // ---- all 6 weight transposes in one launch ----
    Src6 wsrc;
    wsrc.p[0] = Wq; wsrc.p[1] = Wk; wsrc.p[2] = Wv;
    wsrc.p[3] = Wkr; wsrc.p[4] = Wvr; wsrc.p[5] = Wo;
    transpose6_h<<<dim3(DIM / 32, DIM / 32, 6), dim3(32, 8)>>>(wsrc, wth);

    // ---- projections: main QKV in one launch, ref KV in one launch ----
    Gemm3 pm;
    pm.W[0] = wth + 0 * NW; pm.b[0] = bq; pm.C[0] = qlin;
    pm.W[1] = wth + 1 * NW; pm.b[1] = bk; pm.C[1] = klin;
    pm.W[2] = wth + 2 * NW; pm.b[2] = bv; pm.C[2] = vlin;
    gemm_f16_multi<4><<<dim3(36, T_LEN / 128), 256, GEMM_SMEM_M>>>(hsh, pm);

    Gemm3 pr;
    pr.W[0] = wth + 3 * NW; pr.b[0] = bkr; pr.C[0] = krlin;
    pr.W[1] = wth + 4 * NW; pr.b[1] = bvr; pr.C[1] = vrlin;
    pr.W[2] = wth + 3 * NW; pr.b[2] = bkr; pr.C[2] = krlin;  // unused slot
    gemm_f16_multi<2><<<dim3(24, TR_LEN / 64), 256, GEMM_SMEM_R>>>(rhsh, pr);

    // ---- V -> transposed half [h*DH+d][t] ----
    dim3 tb(32, 8);
    transpose_h<<<dim3(DIM / 32, T_LEN / 32),  tb>>>(vlin,  vth,  T_LEN,  DIM);
    transpose_h<<<dim3(DIM / 32, TR_LEN / 32), tb>>>(vrlin, vrth, TR_LEN, DIM);

    // ---- RMSNorms ----
    rmsnorm_kernel<<<T_LEN, 256>>>(qlin,  gq, qlin, qh, scale);
    rmsnorm_kernel<<<T_LEN, 256>>>(klin,  gk, klin, nullptr, 1.f);
    rmsnorm_kernel<<<TR_LEN, 256>>>(krlin, gk, nullptr, krh, 1.f);

    // ---- RoPE -> half ----
    int rope_blocks = (T_LEN * (DIM / 2) + 255) / 256;
    rope_kernel<<<rope_blocks, 256>>>(qlin, qroph, rcos, rsin, scale);
    rope_kernel<<<rope_blocks, 256>>>(klin, kh,    rcos, rsin, 1.f);

    // ---- fused attention (ref + main), half output ----
    dim3 attn_grid(T_LEN / 128, NH);  // (32, 12)
    attn_fused<<<attn_grid, 256, ATT_SMEM>>>(qh, krh, vrth, TR_LEN,
                                             qroph, kh, vth, T_LEN, attnh);

    // ---- output projection ----
    Gemm3 po;
    po.W[0] = wth + 5 * NW; po.b[0] = bo; po.C[0] = out;
    po.W[1] = po.W[0]; po.b[1] = po.b[0]; po.C[1] = out;  // unused
    po.W[2] = po.W[0]; po.b[2] = po.b[0]; po.C[2] = out;  // unused
    gemm_f16_multi<4><<<dim3(12, T_LEN / 128), 256, GEMM_SMEM_M>>>(attnh, po);
}